// round 14
// baseline (speedup 1.0000x reference)
#include <cuda_runtime.h>
#include <math.h>

#define PN 22
#define DN 3
#define HN 64
#define LN 5
#define NWARP 22
#define NTHREADS 704
#define CRC 3.0f       /* 15.0 / 5 layers */
#define LOG2M 7.0f

typedef unsigned long long ull;

/* ---- shared memory layout (floats) ---- */
constexpr int OFF_EW2  = 0;        /* 64*64  col-major + k-swizzle */
constexpr int OFF_CW1  = 4096;     /* 64*64  col-major + k-swizzle */
constexpr int OFF_NW1  = 8192;     /* 128*64 row-major */
constexpr int OFF_NW2  = 16384;    /* 64*64  row-major */
constexpr int OFF_EW1R = 20480;    /* ew1 rows 128,129 -> 128 floats */
constexpr int OFF_EB1  = 20608;
constexpr int OFF_EB2  = 20672;
constexpr int OFF_NB1  = 20736;
constexpr int OFF_NB2  = 20800;
constexpr int OFF_CB1  = 20864;
constexpr int OFF_CW2  = 20928;
constexpr int OFF_AW   = 20992;
constexpr int OFF_AB   = 21056;    /* +pad */
constexpr int OFF_H    = 21060;    /* 2 * 22*64 */
constexpr int OFF_HR   = 23876;
constexpr int OFF_HC   = 26692;
constexpr int OFF_EA   = 29508;    /* 2 * 484 */
constexpr int OFF_CRD  = 30476;    /* 2 * 68 */
constexpr int OFF_CR0  = 30612;
constexpr int OFF_VEL  = 30748;
constexpr int OFF_MEAN = 30884;    /* 8 */
constexpr int OFF_AGG  = 30892;    /* 22 warps * 2 mols * 64 = 2816 */
constexpr int OFF_WB   = 33708;    /* 22 warps * 8 edges * 64 = 11264 floats */
constexpr int SMEM_FLOATS = 44972; /* 179,888 bytes */

__device__ __forceinline__ float sigmf_(float v) {
    return __fdividef(1.f, 1.f + __expf(-v));
}
__device__ __forceinline__ float siluf(float v) { return v * sigmf_(v); }
__device__ __forceinline__ float tanhfast(float v) {
    const float e2 = __expf(2.f * v);
    return 1.f - __fdividef(2.f, e2 + 1.f);
}

__device__ __forceinline__ void ffma2(ull& d, ull a, ull b) {
    asm("fma.rn.f32x2 %0, %1, %2, %0;" : "+l"(d) : "l"(a), "l"(b));
}
__device__ __forceinline__ ull pack2(float x, float y) {
    ull r; asm("mov.b64 %0, {%1, %2};" : "=l"(r) : "f"(x), "f"(y)); return r;
}
__device__ __forceinline__ void unpack2(ull v, float& x, float& y) {
    asm("mov.b64 {%0, %1}, %2;" : "=f"(x), "=f"(y) : "l"(v));
}

/* Whole-warp 8-edge k-paired GEMV, 2 cols/lane, zero packs.
   WmT: 64x64 col-major, swizzled: W[k][c] stored at WmT[c*64 + (k ^ swz(c))],
   swz(c) = ((c>>1)&7)<<2.  Lane owns cols c2=2*lane, c2+1 (both share
   xorv = (lane&7)<<2).  Weight ulonglong2 at kx = k ^ xorv is, after the
   double-XOR, the pair {W[k][c],W[k+1][c]} — conflict-free (8 bank-groups
   per 8-lane phase).  Activations plain, read at plain k (warp broadcast).
   u[e][q] accumulates col c2+q, lo=even-k partial, hi=odd-k partial. */
__device__ __forceinline__ void gemvW8(const float* __restrict__ WmT,
                                       const float* __restrict__ actf,
                                       const int c2, const int xorv, ull u[8][2])
{
#pragma unroll 8
    for (int k = 0; k < HN; k += 4) {
        const int kx = k ^ xorv;
        const ulonglong2 wA = *(const ulonglong2*)&WmT[c2 * HN + kx];
        const ulonglong2 wB = *(const ulonglong2*)&WmT[(c2 + 1) * HN + kx];
#pragma unroll
        for (int e = 0; e < 8; ++e) {
            const ulonglong2 a = *(const ulonglong2*)&actf[e * HN + k];
            ffma2(u[e][0], a.x, wA.x); ffma2(u[e][0], a.y, wA.y);
            ffma2(u[e][1], a.x, wB.x); ffma2(u[e][1], a.y, wB.y);
        }
    }
}

__global__ __launch_bounds__(NTHREADS, 1)
void egnn_kernel(const float* __restrict__ t, const float* __restrict__ x,
                 const float* __restrict__ embW, const float* __restrict__ embb,
                 const float* __restrict__ ew1, const float* __restrict__ eb1,
                 const float* __restrict__ ew2, const float* __restrict__ eb2,
                 const float* __restrict__ nw1, const float* __restrict__ nb1,
                 const float* __restrict__ nw2, const float* __restrict__ nb2,
                 const float* __restrict__ cw1, const float* __restrict__ cb1,
                 const float* __restrict__ cw2, const float* __restrict__ aw,
                 const float* __restrict__ ab, float* __restrict__ out)
{
    extern __shared__ float sm[];
    const int tid = threadIdx.x;
    const int b0 = blockIdx.x * 2;       /* molecules b0, b0+1 */
    const int w = tid >> 5;
    const int lane = tid & 31;
    const int c2 = lane * 2;             /* 2 output cols per lane */
    const int xorv = (lane & 7) << 2;    /* == swz(c2) == swz(c2+1) */
    const int i = w;                     /* node owned by this warp (both mols) */

    /* ---- init: coords, h, edge_attr ---- */
    for (int idx = tid; idx < 2 * PN * DN; idx += NTHREADS) {
        const int m = idx / 66, rem = idx - m * 66;
        const float c = x[(b0 + m) * 66 + rem];
        sm[OFF_CRD + m * 68 + rem] = c;
        sm[OFF_CR0 + m * 68 + rem] = c;
    }
    const float tA = t[b0], tB = t[b0 + 1];
    for (int idx = tid; idx < 2 * PN * HN; idx += NTHREADS) {
        const int m = idx / 1408, q = idx - m * 1408;
        const int ii = q >> 6, o = q & 63;
        const float tb = m ? tB : tA;
        sm[OFF_H + m * 1408 + q] = embW[ii * HN + o] + tb * embW[22 * HN + o]
                                 + LOG2M * embW[23 * HN + o] + embb[o];
    }
    __syncthreads();
    for (int idx = tid; idx < 2 * PN * PN; idx += NTHREADS) {
        const int m = idx / 484, q = idx - m * 484;
        const int ii = q / PN, jj = q - ii * PN;
        const float dx = sm[OFF_CRD + m*68 + ii*3+0] - sm[OFF_CRD + m*68 + jj*3+0];
        const float dy = sm[OFF_CRD + m*68 + ii*3+1] - sm[OFF_CRD + m*68 + jj*3+1];
        const float dz = sm[OFF_CRD + m*68 + ii*3+2] - sm[OFF_CRD + m*68 + jj*3+2];
        sm[OFF_EA + m*484 + q] = dx*dx + dy*dy + dz*dz;
    }
    /* ordered before use by the weight-staging barrier below */

    float* const actm = sm + OFF_WB + w * 512;   /* warp: 8 edges x 64 floats */
    float* const wbf  = actm;                    /* phase-3 scratch (post-pass) */
    float* const aggp = sm + OFF_AGG + w * 128;  /* [mol][64], dedicated */

    for (int l = 0; l < LN; ++l) {
        const float* s1 = ew1 + l * 8320;    /* rows 0..127 read straight from L2 */
        /* ---- stage this layer's weights (ew2/cw1 col-major + k-swizzle) ---- */
        {
            const float* s2 = ew2 + l * 4096;
            for (int q0 = tid; q0 < 4096; q0 += NTHREADS) {
                const int k = q0 >> 6, c = q0 & 63;
                sm[OFF_EW2 + c * 64 + (k ^ (((c >> 1) & 7) << 2))] = s2[q0];
            }
            const float* s5 = cw1 + l * 4096;
            for (int q0 = tid; q0 < 4096; q0 += NTHREADS) {
                const int k = q0 >> 6, c = q0 & 63;
                sm[OFF_CW1 + c * 64 + (k ^ (((c >> 1) & 7) << 2))] = s5[q0];
            }
            const float* s3 = nw1 + l * 8192;
            for (int q0 = tid; q0 < 8192; q0 += NTHREADS) sm[OFF_NW1 + q0] = s3[q0];
            const float* s4 = nw2 + l * 4096;
            for (int q0 = tid; q0 < 4096; q0 += NTHREADS) sm[OFF_NW2 + q0] = s4[q0];
            if (tid < 128) sm[OFF_EW1R + tid] = s1[128 * 64 + tid];
            if (tid >= 128 && tid < 192) {
                const int o = tid - 128;
                sm[OFF_EB1 + o] = eb1[l * 64 + o];
                sm[OFF_EB2 + o] = eb2[l * 64 + o];
                sm[OFF_NB1 + o] = nb1[l * 64 + o];
                sm[OFF_NB2 + o] = nb2[l * 64 + o];
                sm[OFF_CB1 + o] = cb1[l * 64 + o];
                sm[OFF_CW2 + o] = cw2[l * 64 + o];
                sm[OFF_AW + o]  = aw[l * 64 + o];
            }
            if (tid == 0) sm[OFF_AB] = ab[l];
        }
        __syncthreads();

        /* ---- phase 1: Hr/Hc for node i, both molecules (ew1 via L2) ---- */
        {
            ull r2a = 0ull, c2a = 0ull, r2b = 0ull, c2b = 0ull;
            const float* hA = &sm[OFF_H + i * 64];
            const float* hB = &sm[OFF_H + 1408 + i * 64];
#pragma unroll 4
            for (int k = 0; k < HN; ++k) {
                const ull wr = *(const ull*)&s1[k * 64 + c2];
                const ull wc = *(const ull*)&s1[(64 + k) * 64 + c2];
                const float aA = hA[k]; const ull apA = pack2(aA, aA);
                const float aB = hB[k]; const ull apB = pack2(aB, aB);
                ffma2(r2a, apA, wr); ffma2(c2a, apA, wc);
                ffma2(r2b, apB, wr); ffma2(c2b, apB, wc);
            }
            *(ull*)&sm[OFF_HR + i * 64 + c2] = r2a;
            *(ull*)&sm[OFF_HC + i * 64 + c2] = c2a;
            *(ull*)&sm[OFF_HR + 1408 + i * 64 + c2] = r2b;
            *(ull*)&sm[OFF_HC + 1408 + i * 64 + c2] = c2b;
        }
        __syncthreads();

        /* ---- phase 2: 48-slot edge stream (2 mols x 21 + 6 pad),
                8 edges per pass, whole warp, 6 passes ---- */
        float dcA0 = 0.f, dcA1 = 0.f, dcA2 = 0.f;
        float dcB0 = 0.f, dcB1 = 0.f, dcB2 = 0.f;
        float agA0 = 0.f, agA1 = 0.f;
        float agB0 = 0.f, agB1 = 0.f;

#pragma unroll 1
        for (int p = 0; p < 6; ++p) {
            /* setup: t1 = silu(e_in @ ew1 + eb1) -> actm (plain floats) */
            {
                const float2 w128 = *(const float2*)&sm[OFF_EW1R + c2];
                const float2 w129 = *(const float2*)&sm[OFF_EW1R + 64 + c2];
                const float2 b1   = *(const float2*)&sm[OFF_EB1 + c2];
#pragma unroll
                for (int e = 0; e < 8; ++e) {
                    const int eg  = p * 8 + e;
                    const int mol = (eg >= 21) ? 1 : 0;
                    const int r   = eg - mol * 21;
                    const int pad = (r >= PN - 1);
                    int j = (r < i) ? r : r + 1;
                    if (pad) j = i;
                    const int mo68 = mol * 68, mo14 = mol * 1408, mo484 = mol * 484;
                    const float dx = sm[OFF_CRD + mo68 + i*3+0] - sm[OFF_CRD + mo68 + j*3+0];
                    const float dy = sm[OFF_CRD + mo68 + i*3+1] - sm[OFF_CRD + mo68 + j*3+1];
                    const float dz = sm[OFF_CRD + mo68 + i*3+2] - sm[OFF_CRD + mo68 + j*3+2];
                    const float radial = dx*dx + dy*dy + dz*dz;
                    const float eav = sm[OFF_EA + mo484 + i * PN + j];
                    const float2 hr = *(const float2*)&sm[OFF_HR + mo14 + i * 64 + c2];
                    const float2 hc = *(const float2*)&sm[OFF_HC + mo14 + j * 64 + c2];
                    float2 o;
                    o.x = siluf(hr.x + hc.x + b1.x + radial * w128.x + eav * w129.x);
                    o.y = siluf(hr.y + hc.y + b1.y + radial * w128.y + eav * w129.y);
                    *(float2*)&actm[e * HN + c2] = o;
                }
            }
            __syncwarp();

            /* GEMV2: m = silu(t1 @ ew2 + eb2) (k-paired, bias at epilogue) */
            ull u[8][2];
#pragma unroll
            for (int e = 0; e < 8; ++e) { u[e][0] = 0ull; u[e][1] = 0ull; }
            gemvW8(&sm[OFF_EW2], actm, c2, xorv, u);

            const float2 b2  = *(const float2*)&sm[OFF_EB2 + c2];
            const float2 aw2 = *(const float2*)&sm[OFF_AW + c2];
            const float abv  = sm[OFF_AB];
            float m0[8], m1[8], part[8];
#pragma unroll
            for (int e = 0; e < 8; ++e) {
                float l0, h0, l1, h1;
                unpack2(u[e][0], l0, h0); unpack2(u[e][1], l1, h1);
                m0[e] = siluf(l0 + h0 + b2.x);
                m1[e] = siluf(l1 + h1 + b2.y);
                part[e] = m0[e] * aw2.x + m1[e] * aw2.y;
            }
#pragma unroll
            for (int off = 1; off < 32; off <<= 1)
#pragma unroll
                for (int e = 0; e < 8; ++e)
                    part[e] += __shfl_xor_sync(0xffffffffu, part[e], off);
#pragma unroll
            for (int e = 0; e < 8; ++e) {
                const int eg  = p * 8 + e;
                const int mol = (eg >= 21) ? 1 : 0;
                const int pad = (eg - mol * 21 >= PN - 1);
                const float gate = sigmf_(part[e] + abv);
                m0[e] *= gate; m1[e] *= gate;
                if (!pad) {
                    if (mol == 0) { agA0 += m0[e]; agA1 += m1[e]; }
                    else          { agB0 += m0[e]; agB1 += m1[e]; }
                }
            }
            __syncwarp();   /* gemv2 reads of t1 complete */
#pragma unroll
            for (int e = 0; e < 8; ++e) {
                float2 o; o.x = m0[e]; o.y = m1[e];
                *(float2*)&actm[e * HN + c2] = o;
            }
            __syncwarp();

            /* GEMV3: c1 = silu(m @ cw1 + cb1); scal = tanh(c1 @ cw2)*CR */
            ull q[8][2];
#pragma unroll
            for (int e = 0; e < 8; ++e) { q[e][0] = 0ull; q[e][1] = 0ull; }
            gemvW8(&sm[OFF_CW1], actm, c2, xorv, q);

            const float2 cb  = *(const float2*)&sm[OFF_CB1 + c2];
            const float2 cw2f = *(const float2*)&sm[OFF_CW2 + c2];
            float s[8];
#pragma unroll
            for (int e = 0; e < 8; ++e) {
                float l0, h0, l1, h1;
                unpack2(q[e][0], l0, h0); unpack2(q[e][1], l1, h1);
                s[e] = siluf(l0 + h0 + cb.x) * cw2f.x + siluf(l1 + h1 + cb.y) * cw2f.y;
            }
#pragma unroll
            for (int off = 1; off < 32; off <<= 1)
#pragma unroll
                for (int e = 0; e < 8; ++e)
                    s[e] += __shfl_xor_sync(0xffffffffu, s[e], off);
            /* dc: every lane computes identical sums (SIMD-redundant, free) */
#pragma unroll
            for (int e = 0; e < 8; ++e) {
                const int eg  = p * 8 + e;
                const int mol = (eg >= 21) ? 1 : 0;
                const int r   = eg - mol * 21;
                const int pad = (r >= PN - 1);
                int j = (r < i) ? r : r + 1;
                if (pad) j = i;
                const int mo68 = mol * 68;
                const float dx = sm[OFF_CRD + mo68 + i*3+0] - sm[OFF_CRD + mo68 + j*3+0];
                const float dy = sm[OFF_CRD + mo68 + i*3+1] - sm[OFF_CRD + mo68 + j*3+1];
                const float dz = sm[OFF_CRD + mo68 + i*3+2] - sm[OFF_CRD + mo68 + j*3+2];
                const float radial = dx*dx + dy*dy + dz*dz;
                const float inv = 1.f / (sqrtf(radial) + 1.f);
                const float scal = tanhfast(s[e]) * CRC * inv;
                if (mol == 0) { dcA0 += dx*scal; dcA1 += dy*scal; dcA2 += dz*scal; }
                else          { dcB0 += dx*scal; dcB1 += dy*scal; dcB2 += dz*scal; }
            }
            __syncwarp();   /* gemv3 reads done before next pass rewrites actm */
        }

        /* stage agg (cols are per-lane disjoint; no combine needed) */
        {
            float2 a0; a0.x = agA0; a0.y = agA1;
            float2 b0v; b0v.x = agB0; b0v.y = agB1;
            *(float2*)&aggp[c2] = a0;
            *(float2*)&aggp[64 + c2] = b0v;
        }
        __syncthreads();   /* all phase-2 reads of CRD/HR/HC done; agg staged */

        /* ---- phase 3: coord update + node MLP for node i, both molecules ---- */
#pragma unroll
        for (int m = 0; m < 2; ++m) {
            if (lane == 0) {
                sm[OFF_CRD + m * 68 + i * 3 + 0] += m ? dcB0 : dcA0;
                sm[OFF_CRD + m * 68 + i * 3 + 1] += m ? dcB1 : dcA1;
                sm[OFF_CRD + m * 68 + i * 3 + 2] += m ? dcB2 : dcA2;
            }
            ull g2 = *(const ull*)&sm[OFF_NB1 + c2];
#pragma unroll 8
            for (int k = 0; k < HN; ++k) {
                const float a = sm[OFF_H + m * 1408 + i * 64 + k];
                ffma2(g2, pack2(a, a), *(const ull*)&sm[OFF_NW1 + k * HN + c2]);
            }
#pragma unroll 8
            for (int k = 0; k < HN; ++k) {
                const float a = aggp[m * 64 + k];
                ffma2(g2, pack2(a, a), *(const ull*)&sm[OFF_NW1 + (HN + k) * HN + c2]);
            }
            float g0, g1; unpack2(g2, g0, g1);
            g0 = siluf(g0); g1 = siluf(g1);
            wbf[c2] = g0; wbf[c2 + 1] = g1;
            __syncwarp();
            ull o2 = *(const ull*)&sm[OFF_NB2 + c2];
#pragma unroll 8
            for (int k = 0; k < HN; ++k) {
                const float a = wbf[k];
                ffma2(o2, pack2(a, a), *(const ull*)&sm[OFF_NW2 + k * HN + c2]);
            }
            float o0, o1; unpack2(o2, o0, o1);
            __syncwarp();   /* wbf reads complete before m=1 overwrites */
            sm[OFF_H + m * 1408 + i * 64 + c2]     += o0;
            sm[OFF_H + m * 1408 + i * 64 + c2 + 1] += o1;
        }
        __syncthreads();
    } /* layer loop */

    /* ---- velocity + mean removal (both molecules) ---- */
    for (int idx = tid; idx < 2 * PN * DN; idx += NTHREADS) {
        const int m = idx / 66, rem = idx - m * 66;
        sm[OFF_VEL + m * 68 + rem] = sm[OFF_CRD + m * 68 + rem] - sm[OFF_CR0 + m * 68 + rem];
    }
    __syncthreads();
    if (tid < 6) {
        const int m = tid / 3, d = tid - m * 3;
        float s = 0.f;
        for (int k = 0; k < PN; ++k) s += sm[OFF_VEL + m * 68 + k * 3 + d];
        sm[OFF_MEAN + m * 4 + d] = s * (1.f / PN);
    }
    __syncthreads();
    for (int idx = tid; idx < 2 * PN * DN; idx += NTHREADS) {
        const int m = idx / 66, rem = idx - m * 66;
        out[(b0 + m) * 66 + rem] = sm[OFF_VEL + m * 68 + rem] - sm[OFF_MEAN + m * 4 + rem % 3];
    }
}

extern "C" void kernel_launch(void* const* d_in, const int* in_sizes, int n_in,
                              void* d_out, int out_size)
{
    const float* t    = (const float*)d_in[0];
    const float* x    = (const float*)d_in[1];
    const float* embW = (const float*)d_in[2];
    const float* embb = (const float*)d_in[3];
    /* d_in[4] out_W, d_in[5] out_b: dead code (output depends only on coords) */
    const float* ew1  = (const float*)d_in[6];
    const float* eb1  = (const float*)d_in[7];
    const float* ew2  = (const float*)d_in[8];
    const float* eb2  = (const float*)d_in[9];
    const float* nw1  = (const float*)d_in[10];
    const float* nb1  = (const float*)d_in[11];
    const float* nw2  = (const float*)d_in[12];
    const float* nb2  = (const float*)d_in[13];
    const float* cw1  = (const float*)d_in[14];
    const float* cb1  = (const float*)d_in[15];
    const float* cw2  = (const float*)d_in[16];
    const float* aw   = (const float*)d_in[17];
    const float* ab   = (const float*)d_in[18];
    /* d_in[19] rows, d_in[20] cols: structure known analytically */

    const int B = in_sizes[0];
    const size_t smem = (size_t)SMEM_FLOATS * sizeof(float);
    cudaFuncSetAttribute(egnn_kernel, cudaFuncAttributeMaxDynamicSharedMemorySize, (int)smem);
    egnn_kernel<<<B / 2, NTHREADS, smem>>>(t, x, embW, embb, ew1, eb1, ew2, eb2,
                                           nw1, nb1, nw2, nb2, cw1, cb1, cw2, aw, ab,
                                           (float*)d_out);
}

// round 15
// speedup vs baseline: 1.3757x; 1.3757x over previous
#include <cuda_runtime.h>
#include <math.h>

#define PN 22
#define DN 3
#define HN 64
#define LN 5
#define NWARP 22
#define NTHREADS 704
#define CRC 3.0f       /* 15.0 / 5 layers */
#define LOG2M 7.0f

typedef unsigned long long ull;

/* ---- shared memory layout (floats) ---- */
constexpr int OFF_EW2  = 0;        /* 64*64  row-major */
constexpr int OFF_CW1  = 4096;     /* 64*64  row-major */
constexpr int OFF_NW1  = 8192;     /* 128*64 row-major */
constexpr int OFF_NW2  = 16384;    /* 64*64  row-major */
constexpr int OFF_EW1R = 20480;    /* ew1 rows 128,129 -> 128 floats */
constexpr int OFF_EB1  = 20608;
constexpr int OFF_EB2  = 20672;
constexpr int OFF_NB1  = 20736;
constexpr int OFF_NB2  = 20800;
constexpr int OFF_CB1  = 20864;
constexpr int OFF_CW2  = 20928;
constexpr int OFF_AW   = 20992;
constexpr int OFF_AB   = 21056;    /* +pad */
constexpr int OFF_H    = 21060;    /* 2 * 22*64 */
constexpr int OFF_HR   = 23876;
constexpr int OFF_HC   = 26692;
constexpr int OFF_EA   = 29508;    /* 2 * 484 */
constexpr int OFF_CRD  = 30476;    /* 2 * 68 */
constexpr int OFF_CR0  = 30612;
constexpr int OFF_VEL  = 30748;
constexpr int OFF_MEAN = 30884;    /* 8 */
constexpr int OFF_AGG  = 30892;    /* 22 warps * 2 mols * 64 = 2816 */
constexpr int OFF_WB   = 33708;    /* 22 warps * 14 edges * 64 = 19712 floats */
constexpr int SMEM_FLOATS = 53420; /* 213,680 bytes */

__device__ __forceinline__ float sigmf_(float v) {
    return __fdividef(1.f, 1.f + __expf(-v));
}
__device__ __forceinline__ float siluf(float v) { return v * sigmf_(v); }
__device__ __forceinline__ float tanhfast(float v) {
    /* 1 - 2/(e^{2v}+1); overflow-safe */
    const float e2 = __expf(2.f * v);
    return 1.f - __fdividef(2.f, e2 + 1.f);
}

__device__ __forceinline__ void ffma2(ull& d, ull a, ull b) {
    asm("fma.rn.f32x2 %0, %1, %2, %0;" : "+l"(d) : "l"(a), "l"(b));
}
__device__ __forceinline__ ull pack2(float x, float y) {
    ull r; asm("mov.b64 %0, {%1, %2};" : "=l"(r) : "f"(x), "f"(y)); return r;
}
__device__ __forceinline__ void unpack2(ull v, float& x, float& y) {
    asm("mov.b64 {%0, %1}, %2;" : "=f"(x), "=f"(y) : "l"(v));
}

/* 14-edge GEMV (7 per half-warp), 4 cols/lane, float activations.
   Wm: 64x64 row-major. actf: this half's 7 edge rows (64 floats each).
   u[e][0] accumulates cols {c4,c4+1}, u[e][1] cols {c4+2,c4+3}.
   (R10-proven layout: immediate-offset LDS, packs on the fma/alu pipes.) */
__device__ __forceinline__ void gemv7f(const float* __restrict__ Wm,
                                       const float* __restrict__ actf,
                                       const int c4, ull u[7][2])
{
#pragma unroll 4
    for (int k = 0; k < HN; k += 4) {
        const ulonglong2 w0 = *(const ulonglong2*)&Wm[(k + 0) * HN + c4];
        const ulonglong2 w1 = *(const ulonglong2*)&Wm[(k + 1) * HN + c4];
        const ulonglong2 w2 = *(const ulonglong2*)&Wm[(k + 2) * HN + c4];
        const ulonglong2 w3 = *(const ulonglong2*)&Wm[(k + 3) * HN + c4];
#pragma unroll
        for (int e = 0; e < 7; ++e) {
            const float4 a = *(const float4*)&actf[e * HN + k];
            const ull a0 = pack2(a.x, a.x);
            const ull a1 = pack2(a.y, a.y);
            const ull a2 = pack2(a.z, a.z);
            const ull a3 = pack2(a.w, a.w);
            ffma2(u[e][0], a0, w0.x); ffma2(u[e][1], a0, w0.y);
            ffma2(u[e][0], a1, w1.x); ffma2(u[e][1], a1, w1.y);
            ffma2(u[e][0], a2, w2.x); ffma2(u[e][1], a2, w2.y);
            ffma2(u[e][0], a3, w3.x); ffma2(u[e][1], a3, w3.y);
        }
    }
}

__global__ __launch_bounds__(NTHREADS, 1)
void egnn_kernel(const float* __restrict__ t, const float* __restrict__ x,
                 const float* __restrict__ embW, const float* __restrict__ embb,
                 const float* __restrict__ ew1, const float* __restrict__ eb1,
                 const float* __restrict__ ew2, const float* __restrict__ eb2,
                 const float* __restrict__ nw1, const float* __restrict__ nb1,
                 const float* __restrict__ nw2, const float* __restrict__ nb2,
                 const float* __restrict__ cw1, const float* __restrict__ cb1,
                 const float* __restrict__ cw2, const float* __restrict__ aw,
                 const float* __restrict__ ab, float* __restrict__ out)
{
    extern __shared__ float sm[];
    const int tid = threadIdx.x;
    const int b0 = blockIdx.x * 2;       /* molecules b0, b0+1 */
    const int w = tid >> 5;
    const int lane = tid & 31;
    const int hw = lane >> 4;            /* half-warp: edge subset */
    const int c4 = (lane & 15) * 4;      /* 4 output cols per lane */
    const int i = w;                     /* node owned by this warp (both mols) */

    /* ---- init: coords, h, edge_attr ---- */
    for (int idx = tid; idx < 2 * PN * DN; idx += NTHREADS) {
        const int m = idx / 66, rem = idx - m * 66;
        const float c = x[(b0 + m) * 66 + rem];
        sm[OFF_CRD + m * 68 + rem] = c;
        sm[OFF_CR0 + m * 68 + rem] = c;
    }
    const float tA = t[b0], tB = t[b0 + 1];
    for (int idx = tid; idx < 2 * PN * HN; idx += NTHREADS) {
        const int m = idx / 1408, q = idx - m * 1408;
        const int ii = q >> 6, o = q & 63;
        const float tb = m ? tB : tA;
        sm[OFF_H + m * 1408 + q] = embW[ii * HN + o] + tb * embW[22 * HN + o]
                                 + LOG2M * embW[23 * HN + o] + embb[o];
    }
    __syncthreads();
    for (int idx = tid; idx < 2 * PN * PN; idx += NTHREADS) {
        const int m = idx / 484, q = idx - m * 484;
        const int ii = q / PN, jj = q - ii * PN;
        const float dx = sm[OFF_CRD + m*68 + ii*3+0] - sm[OFF_CRD + m*68 + jj*3+0];
        const float dy = sm[OFF_CRD + m*68 + ii*3+1] - sm[OFF_CRD + m*68 + jj*3+1];
        const float dz = sm[OFF_CRD + m*68 + ii*3+2] - sm[OFF_CRD + m*68 + jj*3+2];
        sm[OFF_EA + m*484 + q] = dx*dx + dy*dy + dz*dz;
    }
    /* ordered before use by the weight-staging barrier below */

    float* const actm = sm + OFF_WB + w * 896 + hw * 448;  /* my half: 7x64 */
    float* const wbf  = sm + OFF_WB + w * 896;             /* phase-3 scratch */
    float* const aggp = sm + OFF_AGG + w * 128;            /* [mol][64], dedicated */

    for (int l = 0; l < LN; ++l) {
        const float* s1 = ew1 + l * 8320;    /* rows 0..127 read straight from L2 */
        /* ---- stage this layer's weights ---- */
        {
            const float* s2 = ew2 + l * 4096;
            for (int q = tid; q < 4096; q += NTHREADS) sm[OFF_EW2 + q] = s2[q];
            const float* s5 = cw1 + l * 4096;
            for (int q = tid; q < 4096; q += NTHREADS) sm[OFF_CW1 + q] = s5[q];
            const float* s3 = nw1 + l * 8192;
            for (int q = tid; q < 8192; q += NTHREADS) sm[OFF_NW1 + q] = s3[q];
            const float* s4 = nw2 + l * 4096;
            for (int q = tid; q < 4096; q += NTHREADS) sm[OFF_NW2 + q] = s4[q];
            if (tid < 128) sm[OFF_EW1R + tid] = s1[128 * 64 + tid];
            if (tid >= 128 && tid < 192) {
                const int o = tid - 128;
                sm[OFF_EB1 + o] = eb1[l * 64 + o];
                sm[OFF_EB2 + o] = eb2[l * 64 + o];
                sm[OFF_NB1 + o] = nb1[l * 64 + o];
                sm[OFF_NB2 + o] = nb2[l * 64 + o];
                sm[OFF_CB1 + o] = cb1[l * 64 + o];
                sm[OFF_CW2 + o] = cw2[l * 64 + o];
                sm[OFF_AW + o]  = aw[l * 64 + o];
            }
            if (tid == 0) sm[OFF_AB] = ab[l];
        }
        __syncthreads();

        /* ---- phase 1: Hr/Hc for node i, both molecules (ew1 via L2) ---- */
        {
            ull r2a = 0ull, c2a = 0ull, r2b = 0ull, c2b = 0ull;
            const float* hA = &sm[OFF_H + i * 64];
            const float* hB = &sm[OFF_H + 1408 + i * 64];
#pragma unroll 4
            for (int k = 0; k < HN; ++k) {
                const ull wr = *(const ull*)&s1[k * 64 + 2 * lane];
                const ull wc = *(const ull*)&s1[(64 + k) * 64 + 2 * lane];
                const float aA = hA[k]; const ull apA = pack2(aA, aA);
                const float aB = hB[k]; const ull apB = pack2(aB, aB);
                ffma2(r2a, apA, wr); ffma2(c2a, apA, wc);
                ffma2(r2b, apB, wr); ffma2(c2b, apB, wc);
            }
            *(ull*)&sm[OFF_HR + i * 64 + 2 * lane] = r2a;
            *(ull*)&sm[OFF_HC + i * 64 + 2 * lane] = c2a;
            *(ull*)&sm[OFF_HR + 1408 + i * 64 + 2 * lane] = r2b;
            *(ull*)&sm[OFF_HC + 1408 + i * 64 + 2 * lane] = c2b;
        }
        __syncthreads();

        /* ---- phase 2: exactly 42 edges (2 mols x 21, ZERO pads),
                14 edges per pass (7 per half-warp), 3 passes.
                seg = 2p+hw -> mol and edge base are UNIFORM per half-warp. ---- */
        float dcA0 = 0.f, dcA1 = 0.f, dcA2 = 0.f;
        float dcB0 = 0.f, dcB1 = 0.f, dcB2 = 0.f;
        float agA0 = 0.f, agA1 = 0.f, agA2 = 0.f, agA3 = 0.f;
        float agB0 = 0.f, agB1 = 0.f, agB2 = 0.f, agB3 = 0.f;

#pragma unroll 1
        for (int p = 0; p < 3; ++p) {
            const int seg   = 2 * p + hw;          /* 0..5 */
            const int mol   = (seg >= 3) ? 1 : 0;  /* uniform per half-warp */
            const int rbase = (seg - 3 * mol) * 7; /* edge base 0/7/14 */
            const int mo68 = mol * 68, mo14 = mol * 1408, mo484 = mol * 484;

            /* setup: t1 = silu(e_in @ ew1 + eb1) -> actm (plain floats) */
            {
                const float4 w128 = *(const float4*)&sm[OFF_EW1R + c4];
                const float4 w129 = *(const float4*)&sm[OFF_EW1R + 64 + c4];
                const float4 b1   = *(const float4*)&sm[OFF_EB1 + c4];
                const float4 hr   = *(const float4*)&sm[OFF_HR + mo14 + i * 64 + c4];
                const float cix = sm[OFF_CRD + mo68 + i*3+0];
                const float ciy = sm[OFF_CRD + mo68 + i*3+1];
                const float ciz = sm[OFF_CRD + mo68 + i*3+2];
#pragma unroll
                for (int e = 0; e < 7; ++e) {
                    const int r = rbase + e;           /* 0..20, always valid */
                    const int j = (r < i) ? r : r + 1; /* skip self */
                    const float dx = cix - sm[OFF_CRD + mo68 + j*3+0];
                    const float dy = ciy - sm[OFF_CRD + mo68 + j*3+1];
                    const float dz = ciz - sm[OFF_CRD + mo68 + j*3+2];
                    const float radial = dx*dx + dy*dy + dz*dz;
                    const float eav = sm[OFF_EA + mo484 + i * PN + j];
                    const float4 hc = *(const float4*)&sm[OFF_HC + mo14 + j * 64 + c4];
                    float4 o;
                    o.x = siluf(hr.x + hc.x + b1.x + radial * w128.x + eav * w129.x);
                    o.y = siluf(hr.y + hc.y + b1.y + radial * w128.y + eav * w129.y);
                    o.z = siluf(hr.z + hc.z + b1.z + radial * w128.z + eav * w129.z);
                    o.w = siluf(hr.w + hc.w + b1.w + radial * w128.w + eav * w129.w);
                    *(float4*)&actm[e * HN + c4] = o;
                }
            }
            __syncwarp();

            /* GEMV2: m = silu(t1 @ ew2 + eb2) */
            const float4 b2 = *(const float4*)&sm[OFF_EB2 + c4];
            const ull b2lo = pack2(b2.x, b2.y), b2hi = pack2(b2.z, b2.w);
            ull u[7][2];
#pragma unroll
            for (int e = 0; e < 7; ++e) { u[e][0] = b2lo; u[e][1] = b2hi; }
            gemv7f(&sm[OFF_EW2], actm, c4, u);

            const float4 aw4 = *(const float4*)&sm[OFF_AW + c4];
            const float abv  = sm[OFF_AB];
            float mv[7][4], part[7];
#pragma unroll
            for (int e = 0; e < 7; ++e) {
                unpack2(u[e][0], mv[e][0], mv[e][1]);
                unpack2(u[e][1], mv[e][2], mv[e][3]);
                mv[e][0] = siluf(mv[e][0]); mv[e][1] = siluf(mv[e][1]);
                mv[e][2] = siluf(mv[e][2]); mv[e][3] = siluf(mv[e][3]);
                part[e] = mv[e][0]*aw4.x + mv[e][1]*aw4.y + mv[e][2]*aw4.z + mv[e][3]*aw4.w;
            }
#pragma unroll
            for (int off = 1; off < 16; off <<= 1)
#pragma unroll
                for (int e = 0; e < 7; ++e)
                    part[e] += __shfl_xor_sync(0xffffffffu, part[e], off);
            /* gate + aggregate (mol uniform per half-warp) */
            {
                float a0 = 0.f, a1 = 0.f, a2 = 0.f, a3 = 0.f;
#pragma unroll
                for (int e = 0; e < 7; ++e) {
                    const float gate = sigmf_(part[e] + abv);
                    mv[e][0] *= gate; mv[e][1] *= gate;
                    mv[e][2] *= gate; mv[e][3] *= gate;
                    a0 += mv[e][0]; a1 += mv[e][1]; a2 += mv[e][2]; a3 += mv[e][3];
                }
                if (mol == 0) { agA0 += a0; agA1 += a1; agA2 += a2; agA3 += a3; }
                else          { agB0 += a0; agB1 += a1; agB2 += a2; agB3 += a3; }
            }
            __syncwarp();   /* gemv2 reads of t1 complete */
#pragma unroll
            for (int e = 0; e < 7; ++e) {
                float4 o; o.x = mv[e][0]; o.y = mv[e][1]; o.z = mv[e][2]; o.w = mv[e][3];
                *(float4*)&actm[e * HN + c4] = o;
            }
            __syncwarp();

            /* GEMV3: c1 = silu(m @ cw1 + cb1); scal = tanh(c1 @ cw2)*CR */
            const float4 cb = *(const float4*)&sm[OFF_CB1 + c4];
            const ull cblo = pack2(cb.x, cb.y), cbhi = pack2(cb.z, cb.w);
            ull q[7][2];
#pragma unroll
            for (int e = 0; e < 7; ++e) { q[e][0] = cblo; q[e][1] = cbhi; }
            gemv7f(&sm[OFF_CW1], actm, c4, q);

            const float4 cw4 = *(const float4*)&sm[OFF_CW2 + c4];
            float s[7];
#pragma unroll
            for (int e = 0; e < 7; ++e) {
                float x0, x1, x2, x3;
                unpack2(q[e][0], x0, x1); unpack2(q[e][1], x2, x3);
                s[e] = siluf(x0)*cw4.x + siluf(x1)*cw4.y + siluf(x2)*cw4.z + siluf(x3)*cw4.w;
            }
#pragma unroll
            for (int off = 1; off < 16; off <<= 1)
#pragma unroll
                for (int e = 0; e < 7; ++e)
                    s[e] += __shfl_xor_sync(0xffffffffu, s[e], off);
            {
                const float cix = sm[OFF_CRD + mo68 + i*3+0];
                const float ciy = sm[OFF_CRD + mo68 + i*3+1];
                const float ciz = sm[OFF_CRD + mo68 + i*3+2];
                float d0 = 0.f, d1 = 0.f, d2 = 0.f;
#pragma unroll
                for (int e = 0; e < 7; ++e) {
                    const int r = rbase + e;
                    const int j = (r < i) ? r : r + 1;
                    const float dx = cix - sm[OFF_CRD + mo68 + j*3+0];
                    const float dy = ciy - sm[OFF_CRD + mo68 + j*3+1];
                    const float dz = ciz - sm[OFF_CRD + mo68 + j*3+2];
                    const float radial = dx*dx + dy*dy + dz*dz;
                    const float inv = 1.f / (sqrtf(radial) + 1.f);
                    const float scal = tanhfast(s[e]) * CRC * inv;
                    d0 += dx * scal; d1 += dy * scal; d2 += dz * scal;
                }
                if (mol == 0) { dcA0 += d0; dcA1 += d1; dcA2 += d2; }
                else          { dcB0 += d0; dcB1 += d1; dcB2 += d2; }
            }
            __syncwarp();   /* gemv3 reads done before next pass rewrites actm */
        }

        /* combine half-warps (disjoint edge sets) */
        dcA0 += __shfl_xor_sync(0xffffffffu, dcA0, 16);
        dcA1 += __shfl_xor_sync(0xffffffffu, dcA1, 16);
        dcA2 += __shfl_xor_sync(0xffffffffu, dcA2, 16);
        dcB0 += __shfl_xor_sync(0xffffffffu, dcB0, 16);
        dcB1 += __shfl_xor_sync(0xffffffffu, dcB1, 16);
        dcB2 += __shfl_xor_sync(0xffffffffu, dcB2, 16);
        agA0 += __shfl_xor_sync(0xffffffffu, agA0, 16);
        agA1 += __shfl_xor_sync(0xffffffffu, agA1, 16);
        agA2 += __shfl_xor_sync(0xffffffffu, agA2, 16);
        agA3 += __shfl_xor_sync(0xffffffffu, agA3, 16);
        agB0 += __shfl_xor_sync(0xffffffffu, agB0, 16);
        agB1 += __shfl_xor_sync(0xffffffffu, agB1, 16);
        agB2 += __shfl_xor_sync(0xffffffffu, agB2, 16);
        agB3 += __shfl_xor_sync(0xffffffffu, agB3, 16);
        if (hw == 0) {
            float4 a0; a0.x = agA0; a0.y = agA1; a0.z = agA2; a0.w = agA3;
            float4 b0v; b0v.x = agB0; b0v.y = agB1; b0v.z = agB2; b0v.w = agB3;
            *(float4*)&aggp[c4] = a0;
            *(float4*)&aggp[64 + c4] = b0v;
        }
        __syncthreads();   /* all phase-2 reads of CRD/HR/HC done; agg staged */

        /* ---- phase 3: coord update + node MLP for node i, both molecules ---- */
#pragma unroll
        for (int m = 0; m < 2; ++m) {
            if (lane == 0) {
                sm[OFF_CRD + m * 68 + i * 3 + 0] += m ? dcB0 : dcA0;
                sm[OFF_CRD + m * 68 + i * 3 + 1] += m ? dcB1 : dcA1;
                sm[OFF_CRD + m * 68 + i * 3 + 2] += m ? dcB2 : dcA2;
            }
            ull g2 = *(const ull*)&sm[OFF_NB1 + 2 * lane];
#pragma unroll 8
            for (int k = 0; k < HN; ++k) {
                const float a = sm[OFF_H + m * 1408 + i * 64 + k];
                ffma2(g2, pack2(a, a), *(const ull*)&sm[OFF_NW1 + k * HN + 2 * lane]);
            }
#pragma unroll 8
            for (int k = 0; k < HN; ++k) {
                const float a = aggp[m * 64 + k];
                ffma2(g2, pack2(a, a), *(const ull*)&sm[OFF_NW1 + (HN + k) * HN + 2 * lane]);
            }
            float g0, g1; unpack2(g2, g0, g1);
            g0 = siluf(g0); g1 = siluf(g1);
            wbf[2 * lane] = g0; wbf[2 * lane + 1] = g1;
            __syncwarp();
            ull o2 = *(const ull*)&sm[OFF_NB2 + 2 * lane];
#pragma unroll 8
            for (int k = 0; k < HN; ++k) {
                const float a = wbf[k];
                ffma2(o2, pack2(a, a), *(const ull*)&sm[OFF_NW2 + k * HN + 2 * lane]);
            }
            float o0, o1; unpack2(o2, o0, o1);
            __syncwarp();   /* wbf reads complete before m=1 overwrites */
            sm[OFF_H + m * 1408 + i * 64 + 2 * lane]     += o0;
            sm[OFF_H + m * 1408 + i * 64 + 2 * lane + 1] += o1;
        }
        __syncthreads();
    } /* layer loop */

    /* ---- velocity + mean removal (both molecules) ---- */
    for (int idx = tid; idx < 2 * PN * DN; idx += NTHREADS) {
        const int m = idx / 66, rem = idx - m * 66;
        sm[OFF_VEL + m * 68 + rem] = sm[OFF_CRD + m * 68 + rem] - sm[OFF_CR0 + m * 68 + rem];
    }
    __syncthreads();
    if (tid < 6) {
        const int m = tid / 3, d = tid - m * 3;
        float s = 0.f;
        for (int k = 0; k < PN; ++k) s += sm[OFF_VEL + m * 68 + k * 3 + d];
        sm[OFF_MEAN + m * 4 + d] = s * (1.f / PN);
    }
    __syncthreads();
    for (int idx = tid; idx < 2 * PN * DN; idx += NTHREADS) {
        const int m = idx / 66, rem = idx - m * 66;
        out[(b0 + m) * 66 + rem] = sm[OFF_VEL + m * 68 + rem] - sm[OFF_MEAN + m * 4 + rem % 3];
    }
}

extern "C" void kernel_launch(void* const* d_in, const int* in_sizes, int n_in,
                              void* d_out, int out_size)
{
    const float* t    = (const float*)d_in[0];
    const float* x    = (const float*)d_in[1];
    const float* embW = (const float*)d_in[2];
    const float* embb = (const float*)d_in[3];
    /* d_in[4] out_W, d_in[5] out_b: dead code (output depends only on coords) */
    const float* ew1  = (const float*)d_in[6];
    const float* eb1  = (const float*)d_in[7];
    const float* ew2  = (const float*)d_in[8];
    const float* eb2  = (const float*)d_in[9];
    const float* nw1  = (const float*)d_in[10];
    const float* nb1  = (const float*)d_in[11];
    const float* nw2  = (const float*)d_in[12];
    const float* nb2  = (const float*)d_in[13];
    const float* cw1  = (const float*)d_in[14];
    const float* cb1  = (const float*)d_in[15];
    const float* cw2  = (const float*)d_in[16];
    const float* aw   = (const float*)d_in[17];
    const float* ab   = (const float*)d_in[18];
    /* d_in[19] rows, d_in[20] cols: structure known analytically */

    const int B = in_sizes[0];
    const size_t smem = (size_t)SMEM_FLOATS * sizeof(float);
    cudaFuncSetAttribute(egnn_kernel, cudaFuncAttributeMaxDynamicSharedMemorySize, (int)smem);
    egnn_kernel<<<B / 2, NTHREADS, smem>>>(t, x, embW, embb, ew1, eb1, ew2, eb2,
                                           nw1, nb1, nw2, nb2, cw1, cb1, cw2, aw, ab,
                                           (float*)d_out);
}

// round 16
// speedup vs baseline: 1.4606x; 1.0617x over previous
#include <cuda_runtime.h>
#include <math.h>

#define PN 22
#define DN 3
#define HN 64
#define LN 5
#define NWARP 22
#define NTHREADS 704
#define CRC 3.0f       /* 15.0 / 5 layers */
#define LOG2M 7.0f

typedef unsigned long long ull;

/* ---- shared memory layout (floats) ---- */
constexpr int OFF_EW2  = 0;        /* 64*64  row-major */
constexpr int OFF_CW1  = 4096;     /* 64*64  row-major */
constexpr int OFF_NW1  = 8192;     /* 128*64 row-major */
constexpr int OFF_NW2  = 16384;    /* 64*64  row-major */
constexpr int OFF_EW1R = 20480;    /* ew1 rows 128,129 -> 128 floats */
constexpr int OFF_EB1  = 20608;
constexpr int OFF_EB2  = 20672;
constexpr int OFF_NB1  = 20736;
constexpr int OFF_NB2  = 20800;
constexpr int OFF_CB1  = 20864;
constexpr int OFF_CW2  = 20928;
constexpr int OFF_AW   = 20992;
constexpr int OFF_AB   = 21056;    /* +pad -> 21060 */
constexpr int OFF_H    = 21060;    /* 2 * 22*64 */
constexpr int OFF_HR   = 23876;
constexpr int OFF_HC   = 26692;
constexpr int OFF_EA   = 29508;    /* 2 * 484 */
constexpr int OFF_CRD  = 30476;    /* 2 mols * 22 atoms * 4 (stride-4 padded) */
constexpr int OFF_CR0  = 30660;    /* 2 * 68 (stride 3) */
constexpr int OFF_VEL  = 30796;    /* 2 * 68 */
constexpr int OFF_MEAN = 30932;    /* 8 */
constexpr int OFF_AGG  = 30940;    /* 22 warps * 128 (nd cache during passes; agg after) */
constexpr int OFF_WB   = 33756;    /* 22 warps * 14 edges * 64 = 19712 floats */
constexpr int SMEM_FLOATS = 53468; /* 213,872 bytes */

__device__ __forceinline__ float sigmf_(float v) {
    return __fdividef(1.f, 1.f + __expf(-v));
}
__device__ __forceinline__ float siluf(float v) { return v * sigmf_(v); }
__device__ __forceinline__ float tanhfast(float v) {
    /* 1 - 2/(e^{2v}+1); overflow-safe */
    const float e2 = __expf(2.f * v);
    return 1.f - __fdividef(2.f, e2 + 1.f);
}

__device__ __forceinline__ void ffma2(ull& d, ull a, ull b) {
    asm("fma.rn.f32x2 %0, %1, %2, %0;" : "+l"(d) : "l"(a), "l"(b));
}
__device__ __forceinline__ ull pack2(float x, float y) {
    ull r; asm("mov.b64 %0, {%1, %2};" : "=l"(r) : "f"(x), "f"(y)); return r;
}
__device__ __forceinline__ void unpack2(ull v, float& x, float& y) {
    asm("mov.b64 {%0, %1}, %2;" : "=f"(x), "=f"(y) : "l"(v));
}

/* 14-edge GEMV (7 per half-warp), 4 cols/lane, float activations.
   Wm: 64x64 row-major. actf: this half's 7 edge rows (64 floats each).
   u[e][0] accumulates cols {c4,c4+1}, u[e][1] cols {c4+2,c4+3}.
   (R10/R15-proven layout: immediate-offset LDS, packs on fma/alu pipes.) */
__device__ __forceinline__ void gemv7f(const float* __restrict__ Wm,
                                       const float* __restrict__ actf,
                                       const int c4, ull u[7][2])
{
#pragma unroll 4
    for (int k = 0; k < HN; k += 4) {
        const ulonglong2 w0 = *(const ulonglong2*)&Wm[(k + 0) * HN + c4];
        const ulonglong2 w1 = *(const ulonglong2*)&Wm[(k + 1) * HN + c4];
        const ulonglong2 w2 = *(const ulonglong2*)&Wm[(k + 2) * HN + c4];
        const ulonglong2 w3 = *(const ulonglong2*)&Wm[(k + 3) * HN + c4];
#pragma unroll
        for (int e = 0; e < 7; ++e) {
            const float4 a = *(const float4*)&actf[e * HN + k];
            const ull a0 = pack2(a.x, a.x);
            const ull a1 = pack2(a.y, a.y);
            const ull a2 = pack2(a.z, a.z);
            const ull a3 = pack2(a.w, a.w);
            ffma2(u[e][0], a0, w0.x); ffma2(u[e][1], a0, w0.y);
            ffma2(u[e][0], a1, w1.x); ffma2(u[e][1], a1, w1.y);
            ffma2(u[e][0], a2, w2.x); ffma2(u[e][1], a2, w2.y);
            ffma2(u[e][0], a3, w3.x); ffma2(u[e][1], a3, w3.y);
        }
    }
}

__global__ __launch_bounds__(NTHREADS, 1)
void egnn_kernel(const float* __restrict__ t, const float* __restrict__ x,
                 const float* __restrict__ embW, const float* __restrict__ embb,
                 const float* __restrict__ ew1, const float* __restrict__ eb1,
                 const float* __restrict__ ew2, const float* __restrict__ eb2,
                 const float* __restrict__ nw1, const float* __restrict__ nb1,
                 const float* __restrict__ nw2, const float* __restrict__ nb2,
                 const float* __restrict__ cw1, const float* __restrict__ cb1,
                 const float* __restrict__ cw2, const float* __restrict__ aw,
                 const float* __restrict__ ab, float* __restrict__ out)
{
    extern __shared__ float sm[];
    const int tid = threadIdx.x;
    const int b0 = blockIdx.x * 2;       /* molecules b0, b0+1 */
    const int w = tid >> 5;
    const int lane = tid & 31;
    const int hw = lane >> 4;            /* half-warp: edge subset */
    const int c4 = (lane & 15) * 4;      /* 4 output cols per lane */
    const int i = w;                     /* node owned by this warp (both mols) */

    /* ---- init: coords (stride-4 padded), h, edge_attr ---- */
    for (int idx = tid; idx < 2 * PN * DN; idx += NTHREADS) {
        const int m = idx / 66, rem = idx - m * 66;
        const int a = rem / 3, d = rem - a * 3;
        const float c = x[(b0 + m) * 66 + rem];
        sm[OFF_CRD + m * 92 + a * 4 + d] = c;
        sm[OFF_CR0 + m * 68 + rem] = c;
    }
    const float tA = t[b0], tB = t[b0 + 1];
    for (int idx = tid; idx < 2 * PN * HN; idx += NTHREADS) {
        const int m = idx / 1408, q = idx - m * 1408;
        const int ii = q >> 6, o = q & 63;
        const float tb = m ? tB : tA;
        sm[OFF_H + m * 1408 + q] = embW[ii * HN + o] + tb * embW[22 * HN + o]
                                 + LOG2M * embW[23 * HN + o] + embb[o];
    }
    __syncthreads();
    for (int idx = tid; idx < 2 * PN * PN; idx += NTHREADS) {
        const int m = idx / 484, q = idx - m * 484;
        const int ii = q / PN, jj = q - ii * PN;
        const float dx = sm[OFF_CRD + m*92 + ii*4+0] - sm[OFF_CRD + m*92 + jj*4+0];
        const float dy = sm[OFF_CRD + m*92 + ii*4+1] - sm[OFF_CRD + m*92 + jj*4+1];
        const float dz = sm[OFF_CRD + m*92 + ii*4+2] - sm[OFF_CRD + m*92 + jj*4+2];
        sm[OFF_EA + m*484 + q] = dx*dx + dy*dy + dz*dz;
    }
    /* ordered before use by the weight-staging barrier below */

    float* const actm = sm + OFF_WB + w * 896 + hw * 448;  /* my half: 7x64 */
    float* const wbf  = sm + OFF_WB + w * 896;             /* phase-3 scratch */
    float* const aggp = sm + OFF_AGG + w * 128;            /* nd cache / agg stage */

    for (int l = 0; l < LN; ++l) {
        const float* s1 = ew1 + l * 8320;    /* rows 0..127 read straight from L2 */
        /* ---- stage this layer's weights ---- */
        {
            const float* s2 = ew2 + l * 4096;
            for (int q = tid; q < 4096; q += NTHREADS) sm[OFF_EW2 + q] = s2[q];
            const float* s5 = cw1 + l * 4096;
            for (int q = tid; q < 4096; q += NTHREADS) sm[OFF_CW1 + q] = s5[q];
            const float* s3 = nw1 + l * 8192;
            for (int q = tid; q < 8192; q += NTHREADS) sm[OFF_NW1 + q] = s3[q];
            const float* s4 = nw2 + l * 4096;
            for (int q = tid; q < 4096; q += NTHREADS) sm[OFF_NW2 + q] = s4[q];
            if (tid < 128) sm[OFF_EW1R + tid] = s1[128 * 64 + tid];
            if (tid >= 128 && tid < 192) {
                const int o = tid - 128;
                sm[OFF_EB1 + o] = eb1[l * 64 + o];
                sm[OFF_EB2 + o] = eb2[l * 64 + o];
                sm[OFF_NB1 + o] = nb1[l * 64 + o];
                sm[OFF_NB2 + o] = nb2[l * 64 + o];
                sm[OFF_CB1 + o] = cb1[l * 64 + o];
                sm[OFF_CW2 + o] = cw2[l * 64 + o];
                sm[OFF_AW + o]  = aw[l * 64 + o];
            }
            if (tid == 0) sm[OFF_AB] = ab[l];
        }
        __syncthreads();

        /* ---- phase 1: Hr/Hc for node i, both molecules (ew1 via L2) ---- */
        {
            ull r2a = 0ull, c2a = 0ull, r2b = 0ull, c2b = 0ull;
            const float* hA = &sm[OFF_H + i * 64];
            const float* hB = &sm[OFF_H + 1408 + i * 64];
#pragma unroll 4
            for (int k = 0; k < HN; ++k) {
                const ull wr = *(const ull*)&s1[k * 64 + 2 * lane];
                const ull wc = *(const ull*)&s1[(64 + k) * 64 + 2 * lane];
                const float aA = hA[k]; const ull apA = pack2(aA, aA);
                const float aB = hB[k]; const ull apB = pack2(aB, aB);
                ffma2(r2a, apA, wr); ffma2(c2a, apA, wc);
                ffma2(r2b, apB, wr); ffma2(c2b, apB, wc);
            }
            *(ull*)&sm[OFF_HR + i * 64 + 2 * lane] = r2a;
            *(ull*)&sm[OFF_HC + i * 64 + 2 * lane] = c2a;
            *(ull*)&sm[OFF_HR + 1408 + i * 64 + 2 * lane] = r2b;
            *(ull*)&sm[OFF_HC + 1408 + i * 64 + 2 * lane] = c2b;
        }
        __syncthreads();

        /* ---- phase 2: exactly 42 edges, 14/pass (7 per half-warp), 3 passes.
                seg = 2p+hw -> mol/base uniform per half-warp. ---- */
        float dcA0 = 0.f, dcA1 = 0.f, dcA2 = 0.f;
        float dcB0 = 0.f, dcB1 = 0.f, dcB2 = 0.f;
        float agA0 = 0.f, agA1 = 0.f, agA2 = 0.f, agA3 = 0.f;
        float agB0 = 0.f, agB1 = 0.f, agB2 = 0.f, agB3 = 0.f;

#pragma unroll 1
        for (int p = 0; p < 3; ++p) {
            const int seg   = 2 * p + hw;          /* 0..5 */
            const int mol   = (seg >= 3) ? 1 : 0;  /* uniform per half-warp */
            const int rbase = (seg - 3 * mol) * 7; /* edge base 0/7/14 */
            const int mo92 = mol * 92, mo14 = mol * 1408, mo484 = mol * 484;

            /* setup: t1 = silu(e_in @ ew1 + eb1) -> actm; cache nd in aggp */
            {
                const float4 w128 = *(const float4*)&sm[OFF_EW1R + c4];
                const float4 w129 = *(const float4*)&sm[OFF_EW1R + 64 + c4];
                const float4 b1   = *(const float4*)&sm[OFF_EB1 + c4];
                const float4 hr   = *(const float4*)&sm[OFF_HR + mo14 + i * 64 + c4];
                const float4 ci   = *(const float4*)&sm[OFF_CRD + mo92 + i * 4];
#pragma unroll
                for (int e = 0; e < 7; ++e) {
                    const int r = rbase + e;           /* 0..20, always valid */
                    const int j = (r < i) ? r : r + 1; /* skip self */
                    const float4 cj = *(const float4*)&sm[OFF_CRD + mo92 + j * 4];
                    const float dx = ci.x - cj.x;
                    const float dy = ci.y - cj.y;
                    const float dz = ci.z - cj.z;
                    const float radial = dx*dx + dy*dy + dz*dz;
                    const float inv = 1.f / (sqrtf(radial) + 1.f);
                    if ((lane & 15) == e) {            /* one lane caches nd */
                        float4 nd; nd.x = dx*inv; nd.y = dy*inv; nd.z = dz*inv; nd.w = 0.f;
                        *(float4*)&aggp[hw * 64 + e * 4] = nd;
                    }
                    const float eav = sm[OFF_EA + mo484 + i * PN + j];
                    const float4 hc = *(const float4*)&sm[OFF_HC + mo14 + j * 64 + c4];
                    float4 o;
                    o.x = siluf(hr.x + hc.x + b1.x + radial * w128.x + eav * w129.x);
                    o.y = siluf(hr.y + hc.y + b1.y + radial * w128.y + eav * w129.y);
                    o.z = siluf(hr.z + hc.z + b1.z + radial * w128.z + eav * w129.z);
                    o.w = siluf(hr.w + hc.w + b1.w + radial * w128.w + eav * w129.w);
                    *(float4*)&actm[e * HN + c4] = o;
                }
            }
            __syncwarp();

            /* GEMV2: m = silu(t1 @ ew2 + eb2) */
            const float4 b2 = *(const float4*)&sm[OFF_EB2 + c4];
            const ull b2lo = pack2(b2.x, b2.y), b2hi = pack2(b2.z, b2.w);
            ull u[7][2];
#pragma unroll
            for (int e = 0; e < 7; ++e) { u[e][0] = b2lo; u[e][1] = b2hi; }
            gemv7f(&sm[OFF_EW2], actm, c4, u);

            const float4 aw4 = *(const float4*)&sm[OFF_AW + c4];
            const float abv  = sm[OFF_AB];
            float mv[7][4], part[7];
#pragma unroll
            for (int e = 0; e < 7; ++e) {
                unpack2(u[e][0], mv[e][0], mv[e][1]);
                unpack2(u[e][1], mv[e][2], mv[e][3]);
                mv[e][0] = siluf(mv[e][0]); mv[e][1] = siluf(mv[e][1]);
                mv[e][2] = siluf(mv[e][2]); mv[e][3] = siluf(mv[e][3]);
                part[e] = mv[e][0]*aw4.x + mv[e][1]*aw4.y + mv[e][2]*aw4.z + mv[e][3]*aw4.w;
            }
#pragma unroll
            for (int off = 1; off < 16; off <<= 1)
#pragma unroll
                for (int e = 0; e < 7; ++e)
                    part[e] += __shfl_xor_sync(0xffffffffu, part[e], off);
            /* gate + aggregate (mol uniform per half-warp) */
            {
                float a0 = 0.f, a1 = 0.f, a2 = 0.f, a3 = 0.f;
#pragma unroll
                for (int e = 0; e < 7; ++e) {
                    const float gate = sigmf_(part[e] + abv);
                    mv[e][0] *= gate; mv[e][1] *= gate;
                    mv[e][2] *= gate; mv[e][3] *= gate;
                    a0 += mv[e][0]; a1 += mv[e][1]; a2 += mv[e][2]; a3 += mv[e][3];
                }
                if (mol == 0) { agA0 += a0; agA1 += a1; agA2 += a2; agA3 += a3; }
                else          { agB0 += a0; agB1 += a1; agB2 += a2; agB3 += a3; }
            }
            __syncwarp();   /* gemv2 reads of t1 complete */
#pragma unroll
            for (int e = 0; e < 7; ++e) {
                float4 o; o.x = mv[e][0]; o.y = mv[e][1]; o.z = mv[e][2]; o.w = mv[e][3];
                *(float4*)&actm[e * HN + c4] = o;
            }
            __syncwarp();

            /* GEMV3: c1 = silu(m @ cw1 + cb1); scal = tanh(c1 @ cw2)*CR */
            const float4 cb = *(const float4*)&sm[OFF_CB1 + c4];
            const ull cblo = pack2(cb.x, cb.y), cbhi = pack2(cb.z, cb.w);
            ull q[7][2];
#pragma unroll
            for (int e = 0; e < 7; ++e) { q[e][0] = cblo; q[e][1] = cbhi; }
            gemv7f(&sm[OFF_CW1], actm, c4, q);

            const float4 cw4 = *(const float4*)&sm[OFF_CW2 + c4];
            float s[7];
#pragma unroll
            for (int e = 0; e < 7; ++e) {
                float x0, x1, x2, x3;
                unpack2(q[e][0], x0, x1); unpack2(q[e][1], x2, x3);
                s[e] = siluf(x0)*cw4.x + siluf(x1)*cw4.y + siluf(x2)*cw4.z + siluf(x3)*cw4.w;
            }
#pragma unroll
            for (int off = 1; off < 16; off <<= 1)
#pragma unroll
                for (int e = 0; e < 7; ++e)
                    s[e] += __shfl_xor_sync(0xffffffffu, s[e], off);
            {
                float d0 = 0.f, d1 = 0.f, d2 = 0.f;
#pragma unroll
                for (int e = 0; e < 7; ++e) {
                    const float4 nd = *(const float4*)&aggp[hw * 64 + e * 4];
                    const float scal = tanhfast(s[e]) * CRC;
                    d0 += nd.x * scal; d1 += nd.y * scal; d2 += nd.z * scal;
                }
                if (mol == 0) { dcA0 += d0; dcA1 += d1; dcA2 += d2; }
                else          { dcB0 += d0; dcB1 += d1; dcB2 += d2; }
            }
            __syncwarp();   /* gemv3+nd reads done before next pass rewrites */
        }

        /* combine half-warps (disjoint edge sets) */
        dcA0 += __shfl_xor_sync(0xffffffffu, dcA0, 16);
        dcA1 += __shfl_xor_sync(0xffffffffu, dcA1, 16);
        dcA2 += __shfl_xor_sync(0xffffffffu, dcA2, 16);
        dcB0 += __shfl_xor_sync(0xffffffffu, dcB0, 16);
        dcB1 += __shfl_xor_sync(0xffffffffu, dcB1, 16);
        dcB2 += __shfl_xor_sync(0xffffffffu, dcB2, 16);
        agA0 += __shfl_xor_sync(0xffffffffu, agA0, 16);
        agA1 += __shfl_xor_sync(0xffffffffu, agA1, 16);
        agA2 += __shfl_xor_sync(0xffffffffu, agA2, 16);
        agA3 += __shfl_xor_sync(0xffffffffu, agA3, 16);
        agB0 += __shfl_xor_sync(0xffffffffu, agB0, 16);
        agB1 += __shfl_xor_sync(0xffffffffu, agB1, 16);
        agB2 += __shfl_xor_sync(0xffffffffu, agB2, 16);
        agB3 += __shfl_xor_sync(0xffffffffu, agB3, 16);
        __syncwarp();       /* nd reads done before agg staging overwrites aggp */
        if (hw == 0) {
            float4 a0; a0.x = agA0; a0.y = agA1; a0.z = agA2; a0.w = agA3;
            float4 b0v; b0v.x = agB0; b0v.y = agB1; b0v.z = agB2; b0v.w = agB3;
            *(float4*)&aggp[c4] = a0;
            *(float4*)&aggp[64 + c4] = b0v;
        }
        __syncthreads();   /* all phase-2 reads done; agg staged */

        /* ---- phase 3: coord update + node MLP, BOTH molecules fused ---- */
        {
            if (lane == 0) {
                sm[OFF_CRD + i * 4 + 0] += dcA0;
                sm[OFF_CRD + i * 4 + 1] += dcA1;
                sm[OFF_CRD + i * 4 + 2] += dcA2;
                sm[OFF_CRD + 92 + i * 4 + 0] += dcB0;
                sm[OFF_CRD + 92 + i * 4 + 1] += dcB1;
                sm[OFF_CRD + 92 + i * 4 + 2] += dcB2;
            }
            ull g2a = *(const ull*)&sm[OFF_NB1 + 2 * lane];
            ull g2b = g2a;
#pragma unroll 4
            for (int k = 0; k < HN; k += 4) {
                const float4 aA = *(const float4*)&sm[OFF_H + i * 64 + k];
                const float4 aB = *(const float4*)&sm[OFF_H + 1408 + i * 64 + k];
                const ull w0 = *(const ull*)&sm[OFF_NW1 + (k + 0) * HN + 2 * lane];
                const ull w1 = *(const ull*)&sm[OFF_NW1 + (k + 1) * HN + 2 * lane];
                const ull w2 = *(const ull*)&sm[OFF_NW1 + (k + 2) * HN + 2 * lane];
                const ull w3 = *(const ull*)&sm[OFF_NW1 + (k + 3) * HN + 2 * lane];
                ffma2(g2a, pack2(aA.x, aA.x), w0); ffma2(g2b, pack2(aB.x, aB.x), w0);
                ffma2(g2a, pack2(aA.y, aA.y), w1); ffma2(g2b, pack2(aB.y, aB.y), w1);
                ffma2(g2a, pack2(aA.z, aA.z), w2); ffma2(g2b, pack2(aB.z, aB.z), w2);
                ffma2(g2a, pack2(aA.w, aA.w), w3); ffma2(g2b, pack2(aB.w, aB.w), w3);
            }
#pragma unroll 4
            for (int k = 0; k < HN; k += 4) {
                const float4 aA = *(const float4*)&aggp[k];
                const float4 aB = *(const float4*)&aggp[64 + k];
                const ull w0 = *(const ull*)&sm[OFF_NW1 + (HN + k + 0) * HN + 2 * lane];
                const ull w1 = *(const ull*)&sm[OFF_NW1 + (HN + k + 1) * HN + 2 * lane];
                const ull w2 = *(const ull*)&sm[OFF_NW1 + (HN + k + 2) * HN + 2 * lane];
                const ull w3 = *(const ull*)&sm[OFF_NW1 + (HN + k + 3) * HN + 2 * lane];
                ffma2(g2a, pack2(aA.x, aA.x), w0); ffma2(g2b, pack2(aB.x, aB.x), w0);
                ffma2(g2a, pack2(aA.y, aA.y), w1); ffma2(g2b, pack2(aB.y, aB.y), w1);
                ffma2(g2a, pack2(aA.z, aA.z), w2); ffma2(g2b, pack2(aB.z, aB.z), w2);
                ffma2(g2a, pack2(aA.w, aA.w), w3); ffma2(g2b, pack2(aB.w, aB.w), w3);
            }
            float gA0, gA1, gB0, gB1;
            unpack2(g2a, gA0, gA1); unpack2(g2b, gB0, gB1);
            gA0 = siluf(gA0); gA1 = siluf(gA1);
            gB0 = siluf(gB0); gB1 = siluf(gB1);
            wbf[2 * lane] = gA0; wbf[2 * lane + 1] = gA1;
            wbf[128 + 2 * lane] = gB0; wbf[128 + 2 * lane + 1] = gB1;
            __syncwarp();
            ull o2a = *(const ull*)&sm[OFF_NB2 + 2 * lane];
            ull o2b = o2a;
#pragma unroll 4
            for (int k = 0; k < HN; k += 4) {
                const float4 aA = *(const float4*)&wbf[k];
                const float4 aB = *(const float4*)&wbf[128 + k];
                const ull w0 = *(const ull*)&sm[OFF_NW2 + (k + 0) * HN + 2 * lane];
                const ull w1 = *(const ull*)&sm[OFF_NW2 + (k + 1) * HN + 2 * lane];
                const ull w2 = *(const ull*)&sm[OFF_NW2 + (k + 2) * HN + 2 * lane];
                const ull w3 = *(const ull*)&sm[OFF_NW2 + (k + 3) * HN + 2 * lane];
                ffma2(o2a, pack2(aA.x, aA.x), w0); ffma2(o2b, pack2(aB.x, aB.x), w0);
                ffma2(o2a, pack2(aA.y, aA.y), w1); ffma2(o2b, pack2(aB.y, aB.y), w1);
                ffma2(o2a, pack2(aA.z, aA.z), w2); ffma2(o2b, pack2(aB.z, aB.z), w2);
                ffma2(o2a, pack2(aA.w, aA.w), w3); ffma2(o2b, pack2(aB.w, aB.w), w3);
            }
            float oA0, oA1, oB0, oB1;
            unpack2(o2a, oA0, oA1); unpack2(o2b, oB0, oB1);
            sm[OFF_H + i * 64 + 2 * lane]            += oA0;
            sm[OFF_H + i * 64 + 2 * lane + 1]        += oA1;
            sm[OFF_H + 1408 + i * 64 + 2 * lane]     += oB0;
            sm[OFF_H + 1408 + i * 64 + 2 * lane + 1] += oB1;
        }
        __syncthreads();
    } /* layer loop */

    /* ---- velocity + mean removal (both molecules) ---- */
    for (int idx = tid; idx < 2 * PN * DN; idx += NTHREADS) {
        const int m = idx / 66, rem = idx - m * 66;
        const int a = rem / 3, d = rem - a * 3;
        sm[OFF_VEL + m * 68 + rem] = sm[OFF_CRD + m * 92 + a * 4 + d]
                                   - sm[OFF_CR0 + m * 68 + rem];
    }
    __syncthreads();
    if (tid < 6) {
        const int m = tid / 3, d = tid - m * 3;
        float s = 0.f;
        for (int k = 0; k < PN; ++k) s += sm[OFF_VEL + m * 68 + k * 3 + d];
        sm[OFF_MEAN + m * 4 + d] = s * (1.f / PN);
    }
    __syncthreads();
    for (int idx = tid; idx < 2 * PN * DN; idx += NTHREADS) {
        const int m = idx / 66, rem = idx - m * 66;
        out[(b0 + m) * 66 + rem] = sm[OFF_VEL + m * 68 + rem] - sm[OFF_MEAN + m * 4 + rem % 3];
    }
}

extern "C" void kernel_launch(void* const* d_in, const int* in_sizes, int n_in,
                              void* d_out, int out_size)
{
    const float* t    = (const float*)d_in[0];
    const float* x    = (const float*)d_in[1];
    const float* embW = (const float*)d_in[2];
    const float* embb = (const float*)d_in[3];
    /* d_in[4] out_W, d_in[5] out_b: dead code (output depends only on coords) */
    const float* ew1  = (const float*)d_in[6];
    const float* eb1  = (const float*)d_in[7];
    const float* ew2  = (const float*)d_in[8];
    const float* eb2  = (const float*)d_in[9];
    const float* nw1  = (const float*)d_in[10];
    const float* nb1  = (const float*)d_in[11];
    const float* nw2  = (const float*)d_in[12];
    const float* nb2  = (const float*)d_in[13];
    const float* cw1  = (const float*)d_in[14];
    const float* cb1  = (const float*)d_in[15];
    const float* cw2  = (const float*)d_in[16];
    const float* aw   = (const float*)d_in[17];
    const float* ab   = (const float*)d_in[18];
    /* d_in[19] rows, d_in[20] cols: structure known analytically */

    const int B = in_sizes[0];
    const size_t smem = (size_t)SMEM_FLOATS * sizeof(float);
    cudaFuncSetAttribute(egnn_kernel, cudaFuncAttributeMaxDynamicSharedMemorySize, (int)smem);
    egnn_kernel<<<B / 2, NTHREADS, smem>>>(t, x, embW, embb, ew1, eb1, ew2, eb2,
                                           nw1, nb1, nw2, nb2, cw1, cb1, cw2, aw, ab,
                                           (float*)d_out);
}

// round 17
// speedup vs baseline: 1.4949x; 1.0235x over previous
#include <cuda_runtime.h>
#include <math.h>

#define PN 22
#define DN 3
#define HN 64
#define LN 5
#define NWARP 22
#define NTHREADS 704
#define CRC 3.0f       /* 15.0 / 5 layers */
#define LOG2M 7.0f

typedef unsigned long long ull;

/* ---- shared memory layout (floats) ---- */
constexpr int OFF_EW2  = 0;        /* 64*64  row-major */
constexpr int OFF_CW1  = 4096;     /* 64*64  row-major */
constexpr int OFF_NW1  = 8192;     /* 128*64: ew1 rows 0..127 during phase 1, nw1 after */
constexpr int OFF_NW2  = 16384;    /* 64*64  row-major */
constexpr int OFF_EW1R = 20480;    /* ew1 rows 128,129 -> 128 floats */
constexpr int OFF_EB1  = 20608;
constexpr int OFF_EB2  = 20672;
constexpr int OFF_NB1  = 20736;
constexpr int OFF_NB2  = 20800;
constexpr int OFF_CB1  = 20864;
constexpr int OFF_CW2  = 20928;
constexpr int OFF_AW   = 20992;
constexpr int OFF_AB   = 21056;    /* +pad -> 21060 */
constexpr int OFF_H    = 21060;    /* 2 * 22*64 */
constexpr int OFF_HR   = 23876;
constexpr int OFF_HC   = 26692;
constexpr int OFF_EA   = 29508;    /* 2 * 484 */
constexpr int OFF_CRD  = 30476;    /* 2 mols * 22 atoms * 4 (stride-4 padded) */
constexpr int OFF_CR0  = 30660;    /* 2 * 68 (stride 3) */
constexpr int OFF_VEL  = 30796;    /* 2 * 68 */
constexpr int OFF_MEAN = 30932;    /* 8 */
constexpr int OFF_AGG  = 30940;    /* 22 warps * 128 (nd cache during passes; agg after) */
constexpr int OFF_WB   = 33756;    /* 22 warps * 14 edges * 64 = 19712 floats */
constexpr int SMEM_FLOATS = 53468; /* 213,872 bytes */

__device__ __forceinline__ float sigmf_(float v) {
    return __fdividef(1.f, 1.f + __expf(-v));
}
__device__ __forceinline__ float siluf(float v) { return v * sigmf_(v); }
__device__ __forceinline__ float tanhfast(float v) {
    /* 1 - 2/(e^{2v}+1); overflow-safe */
    const float e2 = __expf(2.f * v);
    return 1.f - __fdividef(2.f, e2 + 1.f);
}

__device__ __forceinline__ void ffma2(ull& d, ull a, ull b) {
    asm("fma.rn.f32x2 %0, %1, %2, %0;" : "+l"(d) : "l"(a), "l"(b));
}
__device__ __forceinline__ ull pack2(float x, float y) {
    ull r; asm("mov.b64 %0, {%1, %2};" : "=l"(r) : "f"(x), "f"(y)); return r;
}
__device__ __forceinline__ void unpack2(ull v, float& x, float& y) {
    asm("mov.b64 {%0, %1}, %2;" : "=f"(x), "=f"(y) : "l"(v));
}

/* 14-edge GEMV (7 per half-warp), 4 cols/lane, float activations.
   Wm: 64x64 row-major. actf: this half's 7 edge rows (64 floats each).
   u[e][0] accumulates cols {c4,c4+1}, u[e][1] cols {c4+2,c4+3}.
   (R10/R15-proven layout: immediate-offset LDS, packs on fma/alu pipes.) */
__device__ __forceinline__ void gemv7f(const float* __restrict__ Wm,
                                       const float* __restrict__ actf,
                                       const int c4, ull u[7][2])
{
#pragma unroll 4
    for (int k = 0; k < HN; k += 4) {
        const ulonglong2 w0 = *(const ulonglong2*)&Wm[(k + 0) * HN + c4];
        const ulonglong2 w1 = *(const ulonglong2*)&Wm[(k + 1) * HN + c4];
        const ulonglong2 w2 = *(const ulonglong2*)&Wm[(k + 2) * HN + c4];
        const ulonglong2 w3 = *(const ulonglong2*)&Wm[(k + 3) * HN + c4];
#pragma unroll
        for (int e = 0; e < 7; ++e) {
            const float4 a = *(const float4*)&actf[e * HN + k];
            const ull a0 = pack2(a.x, a.x);
            const ull a1 = pack2(a.y, a.y);
            const ull a2 = pack2(a.z, a.z);
            const ull a3 = pack2(a.w, a.w);
            ffma2(u[e][0], a0, w0.x); ffma2(u[e][1], a0, w0.y);
            ffma2(u[e][0], a1, w1.x); ffma2(u[e][1], a1, w1.y);
            ffma2(u[e][0], a2, w2.x); ffma2(u[e][1], a2, w2.y);
            ffma2(u[e][0], a3, w3.x); ffma2(u[e][1], a3, w3.y);
        }
    }
}

__global__ __launch_bounds__(NTHREADS, 1)
void egnn_kernel(const float* __restrict__ t, const float* __restrict__ x,
                 const float* __restrict__ embW, const float* __restrict__ embb,
                 const float* __restrict__ ew1, const float* __restrict__ eb1,
                 const float* __restrict__ ew2, const float* __restrict__ eb2,
                 const float* __restrict__ nw1, const float* __restrict__ nb1,
                 const float* __restrict__ nw2, const float* __restrict__ nb2,
                 const float* __restrict__ cw1, const float* __restrict__ cb1,
                 const float* __restrict__ cw2, const float* __restrict__ aw,
                 const float* __restrict__ ab, float* __restrict__ out)
{
    extern __shared__ float sm[];
    const int tid = threadIdx.x;
    const int b0 = blockIdx.x * 2;       /* molecules b0, b0+1 */
    const int w = tid >> 5;
    const int lane = tid & 31;
    const int hw = lane >> 4;            /* half-warp: edge subset */
    const int c4 = (lane & 15) * 4;      /* 4 output cols per lane */
    const int i = w;                     /* node owned by this warp (both mols) */

    /* ---- init: coords (stride-4 padded), h, edge_attr ---- */
    for (int idx = tid; idx < 2 * PN * DN; idx += NTHREADS) {
        const int m = idx / 66, rem = idx - m * 66;
        const int a = rem / 3, d = rem - a * 3;
        const float c = x[(b0 + m) * 66 + rem];
        sm[OFF_CRD + m * 92 + a * 4 + d] = c;
        sm[OFF_CR0 + m * 68 + rem] = c;
    }
    const float tA = t[b0], tB = t[b0 + 1];
    for (int idx = tid; idx < 2 * PN * HN; idx += NTHREADS) {
        const int m = idx / 1408, q = idx - m * 1408;
        const int ii = q >> 6, o = q & 63;
        const float tb = m ? tB : tA;
        sm[OFF_H + m * 1408 + q] = embW[ii * HN + o] + tb * embW[22 * HN + o]
                                 + LOG2M * embW[23 * HN + o] + embb[o];
    }
    __syncthreads();
    for (int idx = tid; idx < 2 * PN * PN; idx += NTHREADS) {
        const int m = idx / 484, q = idx - m * 484;
        const int ii = q / PN, jj = q - ii * PN;
        const float dx = sm[OFF_CRD + m*92 + ii*4+0] - sm[OFF_CRD + m*92 + jj*4+0];
        const float dy = sm[OFF_CRD + m*92 + ii*4+1] - sm[OFF_CRD + m*92 + jj*4+1];
        const float dz = sm[OFF_CRD + m*92 + ii*4+2] - sm[OFF_CRD + m*92 + jj*4+2];
        sm[OFF_EA + m*484 + q] = dx*dx + dy*dy + dz*dz;
    }
    /* ordered before use by the weight-staging barrier below */

    float* const actm = sm + OFF_WB + w * 896 + hw * 448;  /* my half: 7x64 */
    float* const wbf  = sm + OFF_WB + w * 896;             /* phase-3 scratch */
    float* const aggp = sm + OFF_AGG + w * 128;            /* nd cache / agg stage */

    for (int l = 0; l < LN; ++l) {
        /* ---- staging block A: ew1 (rows 0..127 -> NW1 slot!), ew2, cw1, biases.
                float4 copies throughout. ---- */
        {
            const float4* s1v = (const float4*)(ew1 + l * 8320);
            float4* nw1v = (float4*)&sm[OFF_NW1];
            for (int q = tid; q < 2048; q += NTHREADS) nw1v[q] = s1v[q];
            const float4* s2v = (const float4*)(ew2 + l * 4096);
            float4* ew2v = (float4*)&sm[OFF_EW2];
            for (int q = tid; q < 1024; q += NTHREADS) ew2v[q] = s2v[q];
            const float4* s5v = (const float4*)(cw1 + l * 4096);
            float4* cw1v = (float4*)&sm[OFF_CW1];
            for (int q = tid; q < 1024; q += NTHREADS) cw1v[q] = s5v[q];
            if (tid < 32) ((float4*)&sm[OFF_EW1R])[tid] = s1v[2048 + tid];
            if (tid >= 128 && tid < 192) {
                const int o = tid - 128;
                sm[OFF_EB1 + o] = eb1[l * 64 + o];
                sm[OFF_EB2 + o] = eb2[l * 64 + o];
                sm[OFF_NB1 + o] = nb1[l * 64 + o];
                sm[OFF_NB2 + o] = nb2[l * 64 + o];
                sm[OFF_CB1 + o] = cb1[l * 64 + o];
                sm[OFF_CW2 + o] = cw2[l * 64 + o];
                sm[OFF_AW + o]  = aw[l * 64 + o];
            }
            if (tid == 0) sm[OFF_AB] = ab[l];
        }
        __syncthreads();

        /* ---- phase 1: Hr/Hc for node i, both molecules (ew1 from SMEM now) ---- */
        {
            const float* s1s = &sm[OFF_NW1];
            ull r2a = 0ull, c2a = 0ull, r2b = 0ull, c2b = 0ull;
            const float* hA = &sm[OFF_H + i * 64];
            const float* hB = &sm[OFF_H + 1408 + i * 64];
#pragma unroll 4
            for (int k = 0; k < HN; ++k) {
                const ull wr = *(const ull*)&s1s[k * 64 + 2 * lane];
                const ull wc = *(const ull*)&s1s[(64 + k) * 64 + 2 * lane];
                const float aA = hA[k]; const ull apA = pack2(aA, aA);
                const float aB = hB[k]; const ull apB = pack2(aB, aB);
                ffma2(r2a, apA, wr); ffma2(c2a, apA, wc);
                ffma2(r2b, apB, wr); ffma2(c2b, apB, wc);
            }
            *(ull*)&sm[OFF_HR + i * 64 + 2 * lane] = r2a;
            *(ull*)&sm[OFF_HC + i * 64 + 2 * lane] = c2a;
            *(ull*)&sm[OFF_HR + 1408 + i * 64 + 2 * lane] = r2b;
            *(ull*)&sm[OFF_HC + 1408 + i * 64 + 2 * lane] = c2b;
        }
        __syncthreads();   /* HR/HC published; all NW1(ew1) reads complete */

        /* ---- staging block B: nw1/nw2 -> NW1/NW2 (overwrites ew1 copy).
                Issued BEFORE phase 2 so the LDGs drain under phase-2 compute;
                phase 2 never touches NW1/NW2; post-phase-2 barrier publishes
                them for phase 3. ---- */
        {
            const float4* s3v = (const float4*)(nw1 + l * 8192);
            float4* nw1v = (float4*)&sm[OFF_NW1];
            for (int q = tid; q < 2048; q += NTHREADS) nw1v[q] = s3v[q];
            const float4* s4v = (const float4*)(nw2 + l * 4096);
            float4* nw2v = (float4*)&sm[OFF_NW2];
            for (int q = tid; q < 1024; q += NTHREADS) nw2v[q] = s4v[q];
        }

        /* ---- phase 2: exactly 42 edges, 14/pass (7 per half-warp), 3 passes.
                seg = 2p+hw -> mol/base uniform per half-warp. ---- */
        float dcA0 = 0.f, dcA1 = 0.f, dcA2 = 0.f;
        float dcB0 = 0.f, dcB1 = 0.f, dcB2 = 0.f;
        float agA0 = 0.f, agA1 = 0.f, agA2 = 0.f, agA3 = 0.f;
        float agB0 = 0.f, agB1 = 0.f, agB2 = 0.f, agB3 = 0.f;

#pragma unroll 1
        for (int p = 0; p < 3; ++p) {
            const int seg   = 2 * p + hw;          /* 0..5 */
            const int mol   = (seg >= 3) ? 1 : 0;  /* uniform per half-warp */
            const int rbase = (seg - 3 * mol) * 7; /* edge base 0/7/14 */
            const int mo92 = mol * 92, mo14 = mol * 1408, mo484 = mol * 484;

            /* setup: t1 = silu(e_in @ ew1 + eb1) -> actm; cache nd in aggp */
            {
                const float4 w128 = *(const float4*)&sm[OFF_EW1R + c4];
                const float4 w129 = *(const float4*)&sm[OFF_EW1R + 64 + c4];
                const float4 b1   = *(const float4*)&sm[OFF_EB1 + c4];
                const float4 hr   = *(const float4*)&sm[OFF_HR + mo14 + i * 64 + c4];
                const float4 ci   = *(const float4*)&sm[OFF_CRD + mo92 + i * 4];
#pragma unroll
                for (int e = 0; e < 7; ++e) {
                    const int r = rbase + e;           /* 0..20, always valid */
                    const int j = (r < i) ? r : r + 1; /* skip self */
                    const float4 cj = *(const float4*)&sm[OFF_CRD + mo92 + j * 4];
                    const float dx = ci.x - cj.x;
                    const float dy = ci.y - cj.y;
                    const float dz = ci.z - cj.z;
                    const float radial = dx*dx + dy*dy + dz*dz;
                    const float inv = 1.f / (sqrtf(radial) + 1.f);
                    if ((lane & 15) == e) {            /* one lane caches nd */
                        float4 nd; nd.x = dx*inv; nd.y = dy*inv; nd.z = dz*inv; nd.w = 0.f;
                        *(float4*)&aggp[hw * 64 + e * 4] = nd;
                    }
                    const float eav = sm[OFF_EA + mo484 + i * PN + j];
                    const float4 hc = *(const float4*)&sm[OFF_HC + mo14 + j * 64 + c4];
                    float4 o;
                    o.x = siluf(hr.x + hc.x + b1.x + radial * w128.x + eav * w129.x);
                    o.y = siluf(hr.y + hc.y + b1.y + radial * w128.y + eav * w129.y);
                    o.z = siluf(hr.z + hc.z + b1.z + radial * w128.z + eav * w129.z);
                    o.w = siluf(hr.w + hc.w + b1.w + radial * w128.w + eav * w129.w);
                    *(float4*)&actm[e * HN + c4] = o;
                }
            }
            __syncwarp();

            /* GEMV2: m = silu(t1 @ ew2 + eb2) */
            const float4 b2 = *(const float4*)&sm[OFF_EB2 + c4];
            const ull b2lo = pack2(b2.x, b2.y), b2hi = pack2(b2.z, b2.w);
            ull u[7][2];
#pragma unroll
            for (int e = 0; e < 7; ++e) { u[e][0] = b2lo; u[e][1] = b2hi; }
            gemv7f(&sm[OFF_EW2], actm, c4, u);

            const float4 aw4 = *(const float4*)&sm[OFF_AW + c4];
            const float abv  = sm[OFF_AB];
            float mv[7][4], part[7];
#pragma unroll
            for (int e = 0; e < 7; ++e) {
                unpack2(u[e][0], mv[e][0], mv[e][1]);
                unpack2(u[e][1], mv[e][2], mv[e][3]);
                mv[e][0] = siluf(mv[e][0]); mv[e][1] = siluf(mv[e][1]);
                mv[e][2] = siluf(mv[e][2]); mv[e][3] = siluf(mv[e][3]);
                part[e] = mv[e][0]*aw4.x + mv[e][1]*aw4.y + mv[e][2]*aw4.z + mv[e][3]*aw4.w;
            }
#pragma unroll
            for (int off = 1; off < 16; off <<= 1)
#pragma unroll
                for (int e = 0; e < 7; ++e)
                    part[e] += __shfl_xor_sync(0xffffffffu, part[e], off);
            /* gate + aggregate (mol uniform per half-warp) */
            {
                float a0 = 0.f, a1 = 0.f, a2 = 0.f, a3 = 0.f;
#pragma unroll
                for (int e = 0; e < 7; ++e) {
                    const float gate = sigmf_(part[e] + abv);
                    mv[e][0] *= gate; mv[e][1] *= gate;
                    mv[e][2] *= gate; mv[e][3] *= gate;
                    a0 += mv[e][0]; a1 += mv[e][1]; a2 += mv[e][2]; a3 += mv[e][3];
                }
                if (mol == 0) { agA0 += a0; agA1 += a1; agA2 += a2; agA3 += a3; }
                else          { agB0 += a0; agB1 += a1; agB2 += a2; agB3 += a3; }
            }
            __syncwarp();   /* gemv2 reads of t1 complete */
#pragma unroll
            for (int e = 0; e < 7; ++e) {
                float4 o; o.x = mv[e][0]; o.y = mv[e][1]; o.z = mv[e][2]; o.w = mv[e][3];
                *(float4*)&actm[e * HN + c4] = o;
            }
            __syncwarp();

            /* GEMV3: c1 = silu(m @ cw1 + cb1); scal = tanh(c1 @ cw2)*CR */
            const float4 cb = *(const float4*)&sm[OFF_CB1 + c4];
            const ull cblo = pack2(cb.x, cb.y), cbhi = pack2(cb.z, cb.w);
            ull q[7][2];
#pragma unroll
            for (int e = 0; e < 7; ++e) { q[e][0] = cblo; q[e][1] = cbhi; }
            gemv7f(&sm[OFF_CW1], actm, c4, q);

            const float4 cw4 = *(const float4*)&sm[OFF_CW2 + c4];
            float s[7];
#pragma unroll
            for (int e = 0; e < 7; ++e) {
                float x0, x1, x2, x3;
                unpack2(q[e][0], x0, x1); unpack2(q[e][1], x2, x3);
                s[e] = siluf(x0)*cw4.x + siluf(x1)*cw4.y + siluf(x2)*cw4.z + siluf(x3)*cw4.w;
            }
#pragma unroll
            for (int off = 1; off < 16; off <<= 1)
#pragma unroll
                for (int e = 0; e < 7; ++e)
                    s[e] += __shfl_xor_sync(0xffffffffu, s[e], off);
            {
                float d0 = 0.f, d1 = 0.f, d2 = 0.f;
#pragma unroll
                for (int e = 0; e < 7; ++e) {
                    const float4 nd = *(const float4*)&aggp[hw * 64 + e * 4];
                    const float scal = tanhfast(s[e]) * CRC;
                    d0 += nd.x * scal; d1 += nd.y * scal; d2 += nd.z * scal;
                }
                if (mol == 0) { dcA0 += d0; dcA1 += d1; dcA2 += d2; }
                else          { dcB0 += d0; dcB1 += d1; dcB2 += d2; }
            }
            __syncwarp();   /* gemv3+nd reads done before next pass rewrites */
        }

        /* combine half-warps (disjoint edge sets) */
        dcA0 += __shfl_xor_sync(0xffffffffu, dcA0, 16);
        dcA1 += __shfl_xor_sync(0xffffffffu, dcA1, 16);
        dcA2 += __shfl_xor_sync(0xffffffffu, dcA2, 16);
        dcB0 += __shfl_xor_sync(0xffffffffu, dcB0, 16);
        dcB1 += __shfl_xor_sync(0xffffffffu, dcB1, 16);
        dcB2 += __shfl_xor_sync(0xffffffffu, dcB2, 16);
        agA0 += __shfl_xor_sync(0xffffffffu, agA0, 16);
        agA1 += __shfl_xor_sync(0xffffffffu, agA1, 16);
        agA2 += __shfl_xor_sync(0xffffffffu, agA2, 16);
        agA3 += __shfl_xor_sync(0xffffffffu, agA3, 16);
        agB0 += __shfl_xor_sync(0xffffffffu, agB0, 16);
        agB1 += __shfl_xor_sync(0xffffffffu, agB1, 16);
        agB2 += __shfl_xor_sync(0xffffffffu, agB2, 16);
        agB3 += __shfl_xor_sync(0xffffffffu, agB3, 16);
        __syncwarp();       /* nd reads done before agg staging overwrites aggp */
        if (hw == 0) {
            float4 a0; a0.x = agA0; a0.y = agA1; a0.z = agA2; a0.w = agA3;
            float4 b0v; b0v.x = agB0; b0v.y = agB1; b0v.z = agB2; b0v.w = agB3;
            *(float4*)&aggp[c4] = a0;
            *(float4*)&aggp[64 + c4] = b0v;
        }
        __syncthreads();   /* phase-2 reads done; agg staged; nw1/nw2 published */

        /* ---- phase 3: coord update + node MLP, BOTH molecules fused ---- */
        {
            if (lane == 0) {
                sm[OFF_CRD + i * 4 + 0] += dcA0;
                sm[OFF_CRD + i * 4 + 1] += dcA1;
                sm[OFF_CRD + i * 4 + 2] += dcA2;
                sm[OFF_CRD + 92 + i * 4 + 0] += dcB0;
                sm[OFF_CRD + 92 + i * 4 + 1] += dcB1;
                sm[OFF_CRD + 92 + i * 4 + 2] += dcB2;
            }
            ull g2a = *(const ull*)&sm[OFF_NB1 + 2 * lane];
            ull g2b = g2a;
#pragma unroll 4
            for (int k = 0; k < HN; k += 4) {
                const float4 aA = *(const float4*)&sm[OFF_H + i * 64 + k];
                const float4 aB = *(const float4*)&sm[OFF_H + 1408 + i * 64 + k];
                const ull w0 = *(const ull*)&sm[OFF_NW1 + (k + 0) * HN + 2 * lane];
                const ull w1 = *(const ull*)&sm[OFF_NW1 + (k + 1) * HN + 2 * lane];
                const ull w2 = *(const ull*)&sm[OFF_NW1 + (k + 2) * HN + 2 * lane];
                const ull w3 = *(const ull*)&sm[OFF_NW1 + (k + 3) * HN + 2 * lane];
                ffma2(g2a, pack2(aA.x, aA.x), w0); ffma2(g2b, pack2(aB.x, aB.x), w0);
                ffma2(g2a, pack2(aA.y, aA.y), w1); ffma2(g2b, pack2(aB.y, aB.y), w1);
                ffma2(g2a, pack2(aA.z, aA.z), w2); ffma2(g2b, pack2(aB.z, aB.z), w2);
                ffma2(g2a, pack2(aA.w, aA.w), w3); ffma2(g2b, pack2(aB.w, aB.w), w3);
            }
#pragma unroll 4
            for (int k = 0; k < HN; k += 4) {
                const float4 aA = *(const float4*)&aggp[k];
                const float4 aB = *(const float4*)&aggp[64 + k];
                const ull w0 = *(const ull*)&sm[OFF_NW1 + (HN + k + 0) * HN + 2 * lane];
                const ull w1 = *(const ull*)&sm[OFF_NW1 + (HN + k + 1) * HN + 2 * lane];
                const ull w2 = *(const ull*)&sm[OFF_NW1 + (HN + k + 2) * HN + 2 * lane];
                const ull w3 = *(const ull*)&sm[OFF_NW1 + (HN + k + 3) * HN + 2 * lane];
                ffma2(g2a, pack2(aA.x, aA.x), w0); ffma2(g2b, pack2(aB.x, aB.x), w0);
                ffma2(g2a, pack2(aA.y, aA.y), w1); ffma2(g2b, pack2(aB.y, aB.y), w1);
                ffma2(g2a, pack2(aA.z, aA.z), w2); ffma2(g2b, pack2(aB.z, aB.z), w2);
                ffma2(g2a, pack2(aA.w, aA.w), w3); ffma2(g2b, pack2(aB.w, aB.w), w3);
            }
            float gA0, gA1, gB0, gB1;
            unpack2(g2a, gA0, gA1); unpack2(g2b, gB0, gB1);
            gA0 = siluf(gA0); gA1 = siluf(gA1);
            gB0 = siluf(gB0); gB1 = siluf(gB1);
            wbf[2 * lane] = gA0; wbf[2 * lane + 1] = gA1;
            wbf[128 + 2 * lane] = gB0; wbf[128 + 2 * lane + 1] = gB1;
            __syncwarp();
            ull o2a = *(const ull*)&sm[OFF_NB2 + 2 * lane];
            ull o2b = o2a;
#pragma unroll 4
            for (int k = 0; k < HN; k += 4) {
                const float4 aA = *(const float4*)&wbf[k];
                const float4 aB = *(const float4*)&wbf[128 + k];
                const ull w0 = *(const ull*)&sm[OFF_NW2 + (k + 0) * HN + 2 * lane];
                const ull w1 = *(const ull*)&sm[OFF_NW2 + (k + 1) * HN + 2 * lane];
                const ull w2 = *(const ull*)&sm[OFF_NW2 + (k + 2) * HN + 2 * lane];
                const ull w3 = *(const ull*)&sm[OFF_NW2 + (k + 3) * HN + 2 * lane];
                ffma2(o2a, pack2(aA.x, aA.x), w0); ffma2(o2b, pack2(aB.x, aB.x), w0);
                ffma2(o2a, pack2(aA.y, aA.y), w1); ffma2(o2b, pack2(aB.y, aB.y), w1);
                ffma2(o2a, pack2(aA.z, aA.z), w2); ffma2(o2b, pack2(aB.z, aB.z), w2);
                ffma2(o2a, pack2(aA.w, aA.w), w3); ffma2(o2b, pack2(aB.w, aB.w), w3);
            }
            float oA0, oA1, oB0, oB1;
            unpack2(o2a, oA0, oA1); unpack2(o2b, oB0, oB1);
            sm[OFF_H + i * 64 + 2 * lane]            += oA0;
            sm[OFF_H + i * 64 + 2 * lane + 1]        += oA1;
            sm[OFF_H + 1408 + i * 64 + 2 * lane]     += oB0;
            sm[OFF_H + 1408 + i * 64 + 2 * lane + 1] += oB1;
        }
        __syncthreads();
    } /* layer loop */

    /* ---- velocity + mean removal (both molecules) ---- */
    for (int idx = tid; idx < 2 * PN * DN; idx += NTHREADS) {
        const int m = idx / 66, rem = idx - m * 66;
        const int a = rem / 3, d = rem - a * 3;
        sm[OFF_VEL + m * 68 + rem] = sm[OFF_CRD + m * 92 + a * 4 + d]
                                   - sm[OFF_CR0 + m * 68 + rem];
    }
    __syncthreads();
    if (tid < 6) {
        const int m = tid / 3, d = tid - m * 3;
        float s = 0.f;
        for (int k = 0; k < PN; ++k) s += sm[OFF_VEL + m * 68 + k * 3 + d];
        sm[OFF_MEAN + m * 4 + d] = s * (1.f / PN);
    }
    __syncthreads();
    for (int idx = tid; idx < 2 * PN * DN; idx += NTHREADS) {
        const int m = idx / 66, rem = idx - m * 66;
        out[(b0 + m) * 66 + rem] = sm[OFF_VEL + m * 68 + rem] - sm[OFF_MEAN + m * 4 + rem % 3];
    }
}

extern "C" void kernel_launch(void* const* d_in, const int* in_sizes, int n_in,
                              void* d_out, int out_size)
{
    const float* t    = (const float*)d_in[0];
    const float* x    = (const float*)d_in[1];
    const float* embW = (const float*)d_in[2];
    const float* embb = (const float*)d_in[3];
    /* d_in[4] out_W, d_in[5] out_b: dead code (output depends only on coords) */
    const float* ew1  = (const float*)d_in[6];
    const float* eb1  = (const float*)d_in[7];
    const float* ew2  = (const float*)d_in[8];
    const float* eb2  = (const float*)d_in[9];
    const float* nw1  = (const float*)d_in[10];
    const float* nb1  = (const float*)d_in[11];
    const float* nw2  = (const float*)d_in[12];
    const float* nb2  = (const float*)d_in[13];
    const float* cw1  = (const float*)d_in[14];
    const float* cb1  = (const float*)d_in[15];
    const float* cw2  = (const float*)d_in[16];
    const float* aw   = (const float*)d_in[17];
    const float* ab   = (const float*)d_in[18];
    /* d_in[19] rows, d_in[20] cols: structure known analytically */

    const int B = in_sizes[0];
    const size_t smem = (size_t)SMEM_FLOATS * sizeof(float);
    cudaFuncSetAttribute(egnn_kernel, cudaFuncAttributeMaxDynamicSharedMemorySize, (int)smem);
    egnn_kernel<<<B / 2, NTHREADS, smem>>>(t, x, embW, embb, ew1, eb1, ew2, eb2,
                                           nw1, nb1, nw2, nb2, cw1, cb1, cw2, aw, ab,
                                           (float*)d_out);
}